// round 8
// baseline (speedup 1.0000x reference)
#include <cuda_runtime.h>
#include <cuda_fp16.h>
#include <cstdint>

// ============================================================================
// SparseLinear: out[8192,4096] = x[8192,4096] @ (weight*mask)[4096,4096]^T
// fp16 staging + tcgen05 kind::f16 GEMM (sm_103a cubin pass), fp32 TMEM acc.
//
// R8: pipeline reorder. R7 waited MMA(kt-1) completion BEFORE issuing
// MMA(kt) (T/iter ~600cyc = MMA latency). Now: issue MMA(kt) first, then
// wait mbar(kt-1), then overwrite its stage with tile kt+2. Issue-to-issue
// separation -> MMA throughput (256cyc) + overhead, not latency.
// ============================================================================

#define MDIM 8192
#define NDIM 4096
#define KDIM 4096
#define BM 128
#define BN 128
#define BK 64
#define NKT (KDIM / BK)   // 64
#define THREADS 256
#define STAGES 3

__device__ __align__(1024) __half g_A[(size_t)MDIM * KDIM];  // x as fp16
__device__ __align__(1024) __half g_B[(size_t)NDIM * KDIM];  // (w*mask) as fp16
__device__ int g_mask_mode;  // 0 = uint8, 1 = int32, 2 = float32

// ---------------------------------------------------------------------------
// Helpers
// ---------------------------------------------------------------------------
__device__ __forceinline__ uint32_t smem_u32(const void* p) {
    uint32_t a;
    asm("{ .reg .u64 t; cvta.to.shared.u64 t, %1; cvt.u32.u64 %0, t; }"
        : "=r"(a) : "l"(p));
    return a;
}

__device__ __forceinline__ void cp_async16(uint32_t smem, const void* gmem) {
    asm volatile("cp.async.cg.shared.global [%0], [%1], 16;"
                 :: "r"(smem), "l"(gmem) : "memory");
}

// ---------------------------------------------------------------------------
// Mask dtype detection: coalesced uint4 scan of first 64KB.
// ---------------------------------------------------------------------------
__global__ void detect_mask_kernel(const uint4* __restrict__ m) {
    __shared__ int cnt[4];
    if (threadIdx.x < 4) cnt[threadIdx.x] = 0;
    __syncthreads();
    int local[4] = {0, 0, 0, 0};
#pragma unroll
    for (int i = 0; i < 16; i++) {
        uint4 v = m[threadIdx.x + i * 256];
        uint32_t ws[4] = {v.x, v.y, v.z, v.w};
#pragma unroll
        for (int q = 0; q < 4; q++) {
#pragma unroll
            for (int bpos = 0; bpos < 4; bpos++)
                local[bpos] += ((ws[q] >> (8 * bpos)) & 0xFF) ? 1 : 0;
        }
    }
#pragma unroll
    for (int j = 0; j < 4; j++)
        if (local[j]) atomicAdd(&cnt[j], local[j]);
    __syncthreads();
    if (threadIdx.x == 0) {
        int mode;
        if (cnt[1] == 0 && cnt[2] == 0 && cnt[3] == 0) mode = 1;       // int32
        else if (cnt[0] == 0 && cnt[1] == 0)          mode = 2;       // float32
        else                                           mode = 0;       // uint8
        g_mask_mode = mode;
    }
}

// ---------------------------------------------------------------------------
// Prep: f32 -> fp16 conversions
// ---------------------------------------------------------------------------
__global__ void convert_x_kernel(const float* __restrict__ x) {
    const size_t n4 = (size_t)MDIM * KDIM / 4;
    const float4* x4 = (const float4*)x;
    __half2* o = (__half2*)g_A;
    size_t stride = (size_t)gridDim.x * blockDim.x;
    for (size_t j = (size_t)blockIdx.x * blockDim.x + threadIdx.x; j < n4; j += stride) {
        float4 v = x4[j];
        o[2 * j + 0] = __floats2half2_rn(v.x, v.y);
        o[2 * j + 1] = __floats2half2_rn(v.z, v.w);
    }
}

__global__ void convert_w_kernel(const float* __restrict__ w,
                                 const void* __restrict__ mask) {
    const size_t n4 = (size_t)NDIM * KDIM / 4;
    const float4* w4 = (const float4*)w;
    __half2* o = (__half2*)g_B;
    const int mode = g_mask_mode;
    size_t stride = (size_t)gridDim.x * blockDim.x;
    for (size_t j = (size_t)blockIdx.x * blockDim.x + threadIdx.x; j < n4; j += stride) {
        float4 v = w4[j];
        bool k0, k1, k2, k3;
        if (mode == 0) {
            uchar4 m = ((const uchar4*)mask)[j];
            k0 = m.x; k1 = m.y; k2 = m.z; k3 = m.w;
        } else if (mode == 1) {
            int4 m = ((const int4*)mask)[j];
            k0 = m.x; k1 = m.y; k2 = m.z; k3 = m.w;
        } else {
            float4 m = ((const float4*)mask)[j];
            k0 = m.x != 0.f; k1 = m.y != 0.f; k2 = m.z != 0.f; k3 = m.w != 0.f;
        }
        float a = k0 ? v.x : 0.0f;
        float b = k1 ? v.y : 0.0f;
        float c = k2 ? v.z : 0.0f;
        float d = k3 ? v.w : 0.0f;
        o[2 * j + 0] = __floats2half2_rn(a, b);
        o[2 * j + 1] = __floats2half2_rn(c, d);
    }
}

// ---------------------------------------------------------------------------
// tcgen05-only helpers (compiled on the sm_103a cubin pass)
// ---------------------------------------------------------------------------
#if defined(__CUDA_ARCH_FEAT_SM103_ALL)
__device__ __forceinline__ bool elect_one() {
    uint32_t p;
    asm volatile(
        "{\n\t.reg .pred p;\n\t"
        "elect.sync _|p, 0xFFFFFFFF;\n\t"
        "selp.b32 %0, 1, 0, p;\n\t}"
        : "=r"(p));
    return p != 0;
}
__device__ __forceinline__ void mbar_init(uint32_t mbar, uint32_t cnt) {
    asm volatile("mbarrier.init.shared.b64 [%0], %1;" :: "r"(mbar), "r"(cnt) : "memory");
}
__device__ __forceinline__ void mbar_wait(uint32_t mbar, uint32_t parity) {
    asm volatile(
        "{\n\t.reg .pred P1;\n\t"
        "WAIT_%=:\n\t"
        "mbarrier.try_wait.parity.acquire.cta.shared::cta.b64 P1, [%0], %1, 0x989680;\n\t"
        "@P1 bra.uni DONE_%=;\n\t"
        "bra.uni WAIT_%=;\n\t"
        "DONE_%=:\n\t}"
        :: "r"(mbar), "r"(parity) : "memory");
}
__device__ __forceinline__ uint64_t make_desc_sw128(uint32_t addr) {
    uint64_t d = (uint64_t(2) << 61) | (uint64_t(1) << 46) |
                 (uint64_t(64) << 32) | (uint64_t(1) << 16);
    return d | ((uint64_t)(addr >> 4) & 0x3FFF);
}
#define MMA_IDESC ((1u << 4) | ((BN / 8) << 17) | ((BM / 16) << 24))
#endif

// ---------------------------------------------------------------------------
// GEMM kernel: D[M,N] = A[M,K] @ B[N,K]^T
// ---------------------------------------------------------------------------
#define STAGE_BYTES (BM * 128 + BN * 128)             // 16KB A + 16KB B
#define SMEM_DYN_BYTES (STAGES * STAGE_BYTES + 1024)

__global__ void __launch_bounds__(THREADS)
sparse_gemm_kernel(float* __restrict__ out) {
    extern __shared__ char dsmem[];
    const int tid = threadIdx.x;
    const int wid = tid >> 5;
    const int lid = tid & 31;
    const int nt = blockIdx.x;   // N tile
    const int mt = blockIdx.y;   // M tile

    const uint32_t tiles = (smem_u32(dsmem) + 1023u) & ~1023u;

    const __half* gA_base = g_A + (size_t)mt * BM * KDIM;
    const __half* gB_base = g_B + (size_t)nt * BN * KDIM;

    // Tile loader: 1024 x 16B chunks per operand; SW128 swizzle.
    auto load_tile = [&](int kt, int stage) {
        const uint32_t sA = tiles + stage * STAGE_BYTES;
        const uint32_t sB = sA + BM * 128;
        const __half* gA = gA_base + kt * BK;
        const __half* gB = gB_base + kt * BK;
#pragma unroll
        for (int i = 0; i < 4; i++) {
            int c = tid + i * THREADS;        // 0..1023
            int row = c >> 3;
            int col = c & 7;                  // 16B chunk within 128B row
            uint32_t off = (uint32_t)(row << 7) | (uint32_t)(col << 4);
            uint32_t sw = off ^ ((off >> 3) & 0x70);
            size_t goff = (size_t)row * KDIM + col * 8;
            cp_async16(sA + sw, gA + goff);
            cp_async16(sB + sw, gB + goff);
        }
        asm volatile("cp.async.commit_group;" ::: "memory");
    };

#if defined(__CUDA_ARCH_FEAT_SM103_ALL)
    // ======================= tcgen05 path (sm_103a cubin) ==================
    __shared__ uint64_t s_mbar[STAGES];
    __shared__ uint32_t s_tmem_ptr;

    if (wid == 0) {
        asm volatile("tcgen05.alloc.cta_group::1.sync.aligned.shared::cta.b32 [%0], %1;"
                     :: "r"(smem_u32(&s_tmem_ptr)), "r"(128) : "memory");
        asm volatile("tcgen05.relinquish_alloc_permit.cta_group::1.sync.aligned;");
    }
    if (tid < STAGES) mbar_init(smem_u32(&s_mbar[tid]), 1);
    __syncthreads();

    uint32_t tmem;
    asm volatile("ld.shared.b32 %0, [%1];" : "=r"(tmem) : "r"(smem_u32(&s_tmem_ptr)));

    // Prologue: tiles 0 and 1 staged.
    load_tile(0, 0);
    load_tile(1, 1);

    for (int kt = 0; kt < NKT; kt++) {
        const int s = kt % STAGES;

        // 1) Tile kt's cp.async group must be complete (loads for kt+1 may
        //    still be in flight -> allow 1 pending; last iteration: 0).
        if (kt < NKT - 1) asm volatile("cp.async.wait_group 1;" ::: "memory");
        else              asm volatile("cp.async.wait_group 0;" ::: "memory");
        __syncthreads();

        // 2) Issue MMA(kt) immediately (throughput-limited, not latency).
        if (wid == 0 && elect_one()) {
            asm volatile("tcgen05.fence::after_thread_sync;" ::: "memory");
            asm volatile("fence.proxy.async.shared::cta;" ::: "memory");
            const uint32_t stage_base = tiles + s * STAGE_BYTES;
            uint64_t ad = make_desc_sw128(stage_base);
            uint64_t bd = make_desc_sw128(stage_base + BM * 128);
#pragma unroll
            for (int s4 = 0; s4 < 4; s4++) {
                uint32_t en = !(kt == 0 && s4 == 0);
                asm volatile(
                    "{\n\t.reg .pred p;\n\t"
                    "setp.ne.u32 p, %4, 0;\n\t"
                    "tcgen05.mma.cta_group::1.kind::f16 [%0], %1, %2, %3, {%5,%5,%5,%5}, p;\n\t}"
                    :: "r"(tmem), "l"(ad + 2 * s4), "l"(bd + 2 * s4),
                       "r"(MMA_IDESC), "r"(en), "r"(0u) : "memory");
            }
            asm volatile(
                "tcgen05.commit.cta_group::1.mbarrier::arrive::one.shared::cluster.b64 [%0];"
                :: "r"(smem_u32(&s_mbar[s])) : "memory");
        }

        // 3) Before overwriting stage (kt+2)%3 == (kt-1)%3, wait for
        //    MMA(kt-1) to finish reading it (usually already signaled).
        if (kt >= 1 && kt + 2 < NKT)
            mbar_wait(smem_u32(&s_mbar[(kt - 1) % STAGES]),
                      (uint32_t)((kt - 1) / STAGES) & 1u);

        // 4) Prefetch tile kt+2.
        if (kt + 2 < NKT) load_tile(kt + 2, (kt + 2) % STAGES);
    }

    // Final MMA completion wait, then epilogue.
    mbar_wait(smem_u32(&s_mbar[(NKT - 1) % STAGES]),
              (uint32_t)((NKT - 1) / STAGES) & 1u);
    asm volatile("tcgen05.fence::after_thread_sync;" ::: "memory");

    if (wid < 4) {
        const int m = mt * BM + wid * 32 + lid;
        float* orow = out + (size_t)m * NDIM + nt * BN;
        uint32_t r[32];
#pragma unroll
        for (int c4 = 0; c4 < 4; c4++) {
            asm volatile(
                "tcgen05.ld.sync.aligned.32x32b.x32.b32 "
                "{%0,%1,%2,%3,%4,%5,%6,%7,%8,%9,%10,%11,%12,%13,%14,%15,"
                "%16,%17,%18,%19,%20,%21,%22,%23,%24,%25,%26,%27,%28,%29,%30,%31}, [%32];"
                : "=r"(r[0]), "=r"(r[1]), "=r"(r[2]), "=r"(r[3]),
                  "=r"(r[4]), "=r"(r[5]), "=r"(r[6]), "=r"(r[7]),
                  "=r"(r[8]), "=r"(r[9]), "=r"(r[10]), "=r"(r[11]),
                  "=r"(r[12]), "=r"(r[13]), "=r"(r[14]), "=r"(r[15]),
                  "=r"(r[16]), "=r"(r[17]), "=r"(r[18]), "=r"(r[19]),
                  "=r"(r[20]), "=r"(r[21]), "=r"(r[22]), "=r"(r[23]),
                  "=r"(r[24]), "=r"(r[25]), "=r"(r[26]), "=r"(r[27]),
                  "=r"(r[28]), "=r"(r[29]), "=r"(r[30]), "=r"(r[31])
                : "r"(tmem + c4 * 32));
            asm volatile("tcgen05.wait::ld.sync.aligned;" ::: "memory");
            float4* p = (float4*)(orow + c4 * 32);
#pragma unroll
            for (int q = 0; q < 8; q++)
                p[q] = make_float4(__uint_as_float(r[4 * q + 0]),
                                   __uint_as_float(r[4 * q + 1]),
                                   __uint_as_float(r[4 * q + 2]),
                                   __uint_as_float(r[4 * q + 3]));
        }
        asm volatile("tcgen05.fence::before_thread_sync;" ::: "memory");
    }
    __syncthreads();
    if (wid == 0)
        asm volatile("tcgen05.dealloc.cta_group::1.sync.aligned.b32 %0, %1;"
                     :: "r"(tmem), "r"(128));

#else
    // ============ mma.sync fallback (compute_103 PTX pass only) ===========
    const int wm = wid & 1;          // 0..1
    const int wn = wid >> 1;         // 0..3
    const int m_base = wm * 64;
    const int n_base = wn * 32;

    float acc[4][4][4];              // [mi][n8][reg]
#pragma unroll
    for (int i = 0; i < 4; i++)
#pragma unroll
        for (int j = 0; j < 4; j++)
#pragma unroll
            for (int q = 0; q < 4; q++) acc[i][j][q] = 0.0f;

    const uint32_t baseA_off = (uint32_t)(m_base + (lid & 15)) * 128u + (uint32_t)(lid >> 4) * 16u;
    const uint32_t baseB_off = (uint32_t)(n_base + ((lid >> 4) << 3) + (lid & 7)) * 128u +
                               (uint32_t)((lid >> 3) & 1) * 16u;

    load_tile(0, 0);
    load_tile(1, 1);

    for (int kt = 0; kt < NKT; kt++) {
        const int stage = kt % STAGES;
        if (kt < NKT - 2) asm volatile("cp.async.wait_group 1;" ::: "memory");
        else              asm volatile("cp.async.wait_group 0;" ::: "memory");
        __syncthreads();

        if (kt + 2 < NKT) load_tile(kt + 2, (kt + 2) % STAGES);

        const uint32_t sA = tiles + stage * STAGE_BYTES;
        const uint32_t sB = sA + BM * 128;

#pragma unroll
        for (int ks = 0; ks < 4; ks++) {
            uint32_t a[4][4];
#pragma unroll
            for (int mi = 0; mi < 4; mi++) {
                uint32_t off = baseA_off + (uint32_t)mi * 2048u + (uint32_t)ks * 32u;
                uint32_t addr = sA + (off ^ ((off >> 3) & 0x70));
                asm volatile("ldmatrix.sync.aligned.m8n8.x4.shared.b16 {%0,%1,%2,%3}, [%4];"
                             : "=r"(a[mi][0]), "=r"(a[mi][1]), "=r"(a[mi][2]), "=r"(a[mi][3])
                             : "r"(addr));
            }
            uint32_t b[2][4];
#pragma unroll
            for (int nj = 0; nj < 2; nj++) {
                uint32_t off = baseB_off + (uint32_t)nj * 2048u + (uint32_t)ks * 32u;
                uint32_t addr = sB + (off ^ ((off >> 3) & 0x70));
                asm volatile("ldmatrix.sync.aligned.m8n8.x4.shared.b16 {%0,%1,%2,%3}, [%4];"
                             : "=r"(b[nj][0]), "=r"(b[nj][1]), "=r"(b[nj][2]), "=r"(b[nj][3])
                             : "r"(addr));
            }
#pragma unroll
            for (int mi = 0; mi < 4; mi++) {
#pragma unroll
                for (int n8 = 0; n8 < 4; n8++) {
                    uint32_t b0 = b[n8 >> 1][(n8 & 1) * 2 + 0];
                    uint32_t b1 = b[n8 >> 1][(n8 & 1) * 2 + 1];
                    asm volatile(
                        "mma.sync.aligned.m16n8k16.row.col.f32.f16.f16.f32 "
                        "{%0,%1,%2,%3}, {%4,%5,%6,%7}, {%8,%9}, {%0,%1,%2,%3};"
                        : "+f"(acc[mi][n8][0]), "+f"(acc[mi][n8][1]),
                          "+f"(acc[mi][n8][2]), "+f"(acc[mi][n8][3])
                        : "r"(a[mi][0]), "r"(a[mi][1]), "r"(a[mi][2]), "r"(a[mi][3]),
                          "r"(b0), "r"(b1));
                }
            }
        }
    }

    const int tg = lid >> 2;            // 0..7
    const int tc = (lid & 3) * 2;
    float* obase = out + (size_t)(mt * BM + m_base) * NDIM + nt * BN + n_base;
#pragma unroll
    for (int mi = 0; mi < 4; mi++) {
#pragma unroll
        for (int n8 = 0; n8 < 4; n8++) {
            int r0 = mi * 16 + tg;
            int c0 = n8 * 8 + tc;
            float2 v0 = make_float2(acc[mi][n8][0], acc[mi][n8][1]);
            float2 v1 = make_float2(acc[mi][n8][2], acc[mi][n8][3]);
            *(float2*)(obase + (size_t)r0 * NDIM + c0) = v0;
            *(float2*)(obase + (size_t)(r0 + 8) * NDIM + c0) = v1;
        }
    }
#endif
}

// ---------------------------------------------------------------------------
// Launch
// ---------------------------------------------------------------------------
extern "C" void kernel_launch(void* const* d_in, const int* in_sizes, int n_in,
                              void* d_out, int out_size) {
    const float* x = (const float*)d_in[0];
    const float* w = (const float*)d_in[1];
    const void* mask = d_in[2];
    float* out = (float*)d_out;

    cudaFuncSetAttribute(sparse_gemm_kernel,
                         cudaFuncAttributeMaxDynamicSharedMemorySize,
                         SMEM_DYN_BYTES);

    detect_mask_kernel<<<1, 256>>>((const uint4*)mask);
    convert_x_kernel<<<4096, 256>>>(x);
    convert_w_kernel<<<2048, 256>>>(w, mask);

    dim3 grid(NDIM / BN, MDIM / BM);  // (32, 64)
    sparse_gemm_kernel<<<grid, THREADS, SMEM_DYN_BYTES>>>(out);
}

// round 9
// speedup vs baseline: 1.0616x; 1.0616x over previous
#include <cuda_runtime.h>
#include <cuda.h>
#include <cuda_fp16.h>
#include <cstdint>

// ============================================================================
// SparseLinear: out[8192,4096] = x[8192,4096] @ (weight*mask)[4096,4096]^T
// fp16 staging + tcgen05 kind::f16 GEMM (sm_103a cubin pass), fp32 TMEM acc.
//
// R9: kill the per-tile CTA-wide overhead (syncthreads + 2048 cp.async lane
// chunks + swizzle ALU) that held tensor at 42%. Loads now via TMA (2
// UTMALDG/tile), whole mainloop driven by ONE elected thread with mbarriers.
// Tensor maps built host-side via cudaGetDriverEntryPoint (no -lcuda).
// ============================================================================

#define MDIM 8192
#define NDIM 4096
#define KDIM 4096
#define BM 128
#define BN 128
#define BK 64
#define NKT (KDIM / BK)   // 64
#define THREADS 256
#define STAGES 3

__device__ __align__(1024) __half g_A[(size_t)MDIM * KDIM];  // x as fp16
__device__ __align__(1024) __half g_B[(size_t)NDIM * KDIM];  // (w*mask) as fp16
__device__ int g_mask_mode;  // 0 = uint8, 1 = int32, 2 = float32

// ---------------------------------------------------------------------------
// Helpers
// ---------------------------------------------------------------------------
__device__ __forceinline__ uint32_t smem_u32(const void* p) {
    uint32_t a;
    asm("{ .reg .u64 t; cvta.to.shared.u64 t, %1; cvt.u32.u64 %0, t; }"
        : "=r"(a) : "l"(p));
    return a;
}

__device__ __forceinline__ void cp_async16(uint32_t smem, const void* gmem) {
    asm volatile("cp.async.cg.shared.global [%0], [%1], 16;"
                 :: "r"(smem), "l"(gmem) : "memory");
}

// ---------------------------------------------------------------------------
// Mask dtype detection: coalesced uint4 scan of first 64KB.
// ---------------------------------------------------------------------------
__global__ void detect_mask_kernel(const uint4* __restrict__ m) {
    __shared__ int cnt[4];
    if (threadIdx.x < 4) cnt[threadIdx.x] = 0;
    __syncthreads();
    int local[4] = {0, 0, 0, 0};
#pragma unroll
    for (int i = 0; i < 16; i++) {
        uint4 v = m[threadIdx.x + i * 256];
        uint32_t ws[4] = {v.x, v.y, v.z, v.w};
#pragma unroll
        for (int q = 0; q < 4; q++) {
#pragma unroll
            for (int bpos = 0; bpos < 4; bpos++)
                local[bpos] += ((ws[q] >> (8 * bpos)) & 0xFF) ? 1 : 0;
        }
    }
#pragma unroll
    for (int j = 0; j < 4; j++)
        if (local[j]) atomicAdd(&cnt[j], local[j]);
    __syncthreads();
    if (threadIdx.x == 0) {
        int mode;
        if (cnt[1] == 0 && cnt[2] == 0 && cnt[3] == 0) mode = 1;       // int32
        else if (cnt[0] == 0 && cnt[1] == 0)          mode = 2;       // float32
        else                                           mode = 0;       // uint8
        g_mask_mode = mode;
    }
}

// ---------------------------------------------------------------------------
// Prep: f32 -> fp16 conversions
// ---------------------------------------------------------------------------
__global__ void convert_x_kernel(const float* __restrict__ x) {
    const size_t n4 = (size_t)MDIM * KDIM / 4;
    const float4* x4 = (const float4*)x;
    __half2* o = (__half2*)g_A;
    size_t stride = (size_t)gridDim.x * blockDim.x;
    for (size_t j = (size_t)blockIdx.x * blockDim.x + threadIdx.x; j < n4; j += stride) {
        float4 v = x4[j];
        o[2 * j + 0] = __floats2half2_rn(v.x, v.y);
        o[2 * j + 1] = __floats2half2_rn(v.z, v.w);
    }
}

__global__ void convert_w_kernel(const float* __restrict__ w,
                                 const void* __restrict__ mask) {
    const size_t n4 = (size_t)NDIM * KDIM / 4;
    const float4* w4 = (const float4*)w;
    __half2* o = (__half2*)g_B;
    const int mode = g_mask_mode;
    size_t stride = (size_t)gridDim.x * blockDim.x;
    for (size_t j = (size_t)blockIdx.x * blockDim.x + threadIdx.x; j < n4; j += stride) {
        float4 v = w4[j];
        bool k0, k1, k2, k3;
        if (mode == 0) {
            uchar4 m = ((const uchar4*)mask)[j];
            k0 = m.x; k1 = m.y; k2 = m.z; k3 = m.w;
        } else if (mode == 1) {
            int4 m = ((const int4*)mask)[j];
            k0 = m.x; k1 = m.y; k2 = m.z; k3 = m.w;
        } else {
            float4 m = ((const float4*)mask)[j];
            k0 = m.x != 0.f; k1 = m.y != 0.f; k2 = m.z != 0.f; k3 = m.w != 0.f;
        }
        float a = k0 ? v.x : 0.0f;
        float b = k1 ? v.y : 0.0f;
        float c = k2 ? v.z : 0.0f;
        float d = k3 ? v.w : 0.0f;
        o[2 * j + 0] = __floats2half2_rn(a, b);
        o[2 * j + 1] = __floats2half2_rn(c, d);
    }
}

// ---------------------------------------------------------------------------
// tcgen05-only helpers (compiled on the sm_103a cubin pass)
// ---------------------------------------------------------------------------
#if defined(__CUDA_ARCH_FEAT_SM103_ALL)
__device__ __forceinline__ bool elect_one() {
    uint32_t p;
    asm volatile(
        "{\n\t.reg .pred p;\n\t"
        "elect.sync _|p, 0xFFFFFFFF;\n\t"
        "selp.b32 %0, 1, 0, p;\n\t}"
        : "=r"(p));
    return p != 0;
}
__device__ __forceinline__ void mbar_init(uint32_t mbar, uint32_t cnt) {
    asm volatile("mbarrier.init.shared.b64 [%0], %1;" :: "r"(mbar), "r"(cnt) : "memory");
}
__device__ __forceinline__ void mbar_wait(uint32_t mbar, uint32_t parity) {
    asm volatile(
        "{\n\t.reg .pred P1;\n\t"
        "WAIT_%=:\n\t"
        "mbarrier.try_wait.parity.acquire.cta.shared::cta.b64 P1, [%0], %1, 0x989680;\n\t"
        "@P1 bra.uni DONE_%=;\n\t"
        "bra.uni WAIT_%=;\n\t"
        "DONE_%=:\n\t}"
        :: "r"(mbar), "r"(parity) : "memory");
}
__device__ __forceinline__ void mbar_expect_tx(uint32_t mbar, uint32_t bytes) {
    asm volatile("mbarrier.arrive.expect_tx.shared.b64 _, [%0], %1;"
                 :: "r"(mbar), "r"(bytes) : "memory");
}
__device__ __forceinline__ void tma_load_2d(uint32_t smem, const void* tm,
                                            int32_t x, int32_t y, uint32_t mbar) {
    asm volatile(
        "cp.async.bulk.tensor.2d.shared::cta.global.tile.mbarrier::complete_tx::bytes "
        "[%0], [%1, {%2, %3}], [%4];"
        :: "r"(smem), "l"(tm), "r"(x), "r"(y), "r"(mbar) : "memory");
}
__device__ __forceinline__ uint64_t make_desc_sw128(uint32_t addr) {
    uint64_t d = (uint64_t(2) << 61) | (uint64_t(1) << 46) |
                 (uint64_t(64) << 32) | (uint64_t(1) << 16);
    return d | ((uint64_t)(addr >> 4) & 0x3FFF);
}
#define MMA_IDESC ((1u << 4) | ((BN / 8) << 17) | ((BM / 16) << 24))
#endif

// ---------------------------------------------------------------------------
// GEMM kernel: D[M,N] = A[M,K] @ B[N,K]^T
// ---------------------------------------------------------------------------
#define STAGE_BYTES (BM * 128 + BN * 128)             // 16KB A + 16KB B
#define SMEM_DYN_BYTES (STAGES * STAGE_BYTES + 1024)

__global__ void __launch_bounds__(THREADS)
sparse_gemm_kernel(float* __restrict__ out,
                   const __grid_constant__ CUtensorMap tmA,
                   const __grid_constant__ CUtensorMap tmB) {
    extern __shared__ char dsmem[];
    const int tid = threadIdx.x;
    const int wid = tid >> 5;
    const int lid = tid & 31;
    const int nt = blockIdx.x;   // N tile
    const int mt = blockIdx.y;   // M tile

    const uint32_t tiles = (smem_u32(dsmem) + 1023u) & ~1023u;

#if defined(__CUDA_ARCH_FEAT_SM103_ALL)
    // ======================= tcgen05 + TMA path (sm_103a cubin) ============
    __shared__ uint64_t s_full[STAGES];   // TMA completion (expect_tx)
    __shared__ uint64_t s_mma[STAGES];    // MMA completion (commit)
    __shared__ uint32_t s_tmem_ptr;

    if (wid == 0) {
        asm volatile("tcgen05.alloc.cta_group::1.sync.aligned.shared::cta.b32 [%0], %1;"
                     :: "r"(smem_u32(&s_tmem_ptr)), "r"(128) : "memory");
        asm volatile("tcgen05.relinquish_alloc_permit.cta_group::1.sync.aligned;");
    }
    if (tid == 0) {
#pragma unroll
        for (int s = 0; s < STAGES; s++) {
            mbar_init(smem_u32(&s_full[s]), 1);
            mbar_init(smem_u32(&s_mma[s]), 1);
        }
        asm volatile("fence.proxy.async.shared::cta;" ::: "memory");
    }
    __syncthreads();

    uint32_t tmem;
    asm volatile("ld.shared.b32 %0, [%1];" : "=r"(tmem) : "r"(smem_u32(&s_tmem_ptr)));

    if (wid == 0 && elect_one()) {
        // Prologue: TMA tiles 0, 1.
#pragma unroll
        for (int p = 0; p < 2; p++) {
            const uint32_t sb = tiles + p * STAGE_BYTES;
            mbar_expect_tx(smem_u32(&s_full[p]), STAGE_BYTES);
            tma_load_2d(sb, &tmA, p * BK, mt * BM, smem_u32(&s_full[p]));
            tma_load_2d(sb + BM * 128, &tmB, p * BK, nt * BN, smem_u32(&s_full[p]));
        }

        for (int kt = 0; kt < NKT; kt++) {
            const int s = kt % STAGES;

            // 1) Tile kt's TMA done.
            mbar_wait(smem_u32(&s_full[s]), (uint32_t)(kt / STAGES) & 1u);

            // 2) Issue MMA(kt), commit completion to s_mma[s].
            const uint32_t stage_base = tiles + s * STAGE_BYTES;
            uint64_t ad = make_desc_sw128(stage_base);
            uint64_t bd = make_desc_sw128(stage_base + BM * 128);
#pragma unroll
            for (int s4 = 0; s4 < 4; s4++) {
                uint32_t en = !(kt == 0 && s4 == 0);
                asm volatile(
                    "{\n\t.reg .pred p;\n\t"
                    "setp.ne.u32 p, %4, 0;\n\t"
                    "tcgen05.mma.cta_group::1.kind::f16 [%0], %1, %2, %3, {%5,%5,%5,%5}, p;\n\t}"
                    :: "r"(tmem), "l"(ad + 2 * s4), "l"(bd + 2 * s4),
                       "r"(MMA_IDESC), "r"(en), "r"(0u) : "memory");
            }
            asm volatile(
                "tcgen05.commit.cta_group::1.mbarrier::arrive::one.shared::cluster.b64 [%0];"
                :: "r"(smem_u32(&s_mma[s])) : "memory");

            // 3) Prefetch tile kt+2 into stage (kt+2)%3; if that stage was
            //    used by MMA(kt-1), wait for it first (usually signaled).
            if (kt + 2 < NKT) {
                const int st = (kt + 2) % STAGES;
                if (kt >= 1)
                    mbar_wait(smem_u32(&s_mma[(kt - 1) % STAGES]),
                              (uint32_t)((kt - 1) / STAGES) & 1u);
                const uint32_t sb = tiles + st * STAGE_BYTES;
                mbar_expect_tx(smem_u32(&s_full[st]), STAGE_BYTES);
                tma_load_2d(sb, &tmA, (kt + 2) * BK, mt * BM, smem_u32(&s_full[st]));
                tma_load_2d(sb + BM * 128, &tmB, (kt + 2) * BK, nt * BN,
                            smem_u32(&s_full[st]));
            }
        }

        // Final MMA completion (elected thread observed every phase in order).
        mbar_wait(smem_u32(&s_mma[(NKT - 1) % STAGES]),
                  (uint32_t)((NKT - 1) / STAGES) & 1u);
    }

    // All threads rendezvous; after this, TMEM D is complete.
    __syncthreads();
    asm volatile("tcgen05.fence::after_thread_sync;" ::: "memory");

    if (wid < 4) {
        const int m = mt * BM + wid * 32 + lid;
        float* orow = out + (size_t)m * NDIM + nt * BN;
        uint32_t r[32];
#pragma unroll
        for (int c4 = 0; c4 < 4; c4++) {
            asm volatile(
                "tcgen05.ld.sync.aligned.32x32b.x32.b32 "
                "{%0,%1,%2,%3,%4,%5,%6,%7,%8,%9,%10,%11,%12,%13,%14,%15,"
                "%16,%17,%18,%19,%20,%21,%22,%23,%24,%25,%26,%27,%28,%29,%30,%31}, [%32];"
                : "=r"(r[0]), "=r"(r[1]), "=r"(r[2]), "=r"(r[3]),
                  "=r"(r[4]), "=r"(r[5]), "=r"(r[6]), "=r"(r[7]),
                  "=r"(r[8]), "=r"(r[9]), "=r"(r[10]), "=r"(r[11]),
                  "=r"(r[12]), "=r"(r[13]), "=r"(r[14]), "=r"(r[15]),
                  "=r"(r[16]), "=r"(r[17]), "=r"(r[18]), "=r"(r[19]),
                  "=r"(r[20]), "=r"(r[21]), "=r"(r[22]), "=r"(r[23]),
                  "=r"(r[24]), "=r"(r[25]), "=r"(r[26]), "=r"(r[27]),
                  "=r"(r[28]), "=r"(r[29]), "=r"(r[30]), "=r"(r[31])
                : "r"(tmem + c4 * 32));
            asm volatile("tcgen05.wait::ld.sync.aligned;" ::: "memory");
            float4* p = (float4*)(orow + c4 * 32);
#pragma unroll
            for (int q = 0; q < 8; q++)
                p[q] = make_float4(__uint_as_float(r[4 * q + 0]),
                                   __uint_as_float(r[4 * q + 1]),
                                   __uint_as_float(r[4 * q + 2]),
                                   __uint_as_float(r[4 * q + 3]));
        }
        asm volatile("tcgen05.fence::before_thread_sync;" ::: "memory");
    }
    __syncthreads();
    if (wid == 0)
        asm volatile("tcgen05.dealloc.cta_group::1.sync.aligned.b32 %0, %1;"
                     :: "r"(tmem), "r"(128));

#else
    // ============ mma.sync fallback (compute_103 PTX pass only) ===========
    const __half* gA_base = g_A + (size_t)mt * BM * KDIM;
    const __half* gB_base = g_B + (size_t)nt * BN * KDIM;

    auto load_tile = [&](int kt, int stage) {
        const uint32_t sA = tiles + stage * STAGE_BYTES;
        const uint32_t sB = sA + BM * 128;
        const __half* gA = gA_base + kt * BK;
        const __half* gB = gB_base + kt * BK;
#pragma unroll
        for (int i = 0; i < 4; i++) {
            int c = tid + i * THREADS;        // 0..1023
            int row = c >> 3;
            int col = c & 7;
            uint32_t off = (uint32_t)(row << 7) | (uint32_t)(col << 4);
            uint32_t sw = off ^ ((off >> 3) & 0x70);
            size_t goff = (size_t)row * KDIM + col * 8;
            cp_async16(sA + sw, gA + goff);
            cp_async16(sB + sw, gB + goff);
        }
        asm volatile("cp.async.commit_group;" ::: "memory");
    };

    const int wm = wid & 1;
    const int wn = wid >> 1;
    const int m_base = wm * 64;
    const int n_base = wn * 32;

    float acc[4][4][4];
#pragma unroll
    for (int i = 0; i < 4; i++)
#pragma unroll
        for (int j = 0; j < 4; j++)
#pragma unroll
            for (int q = 0; q < 4; q++) acc[i][j][q] = 0.0f;

    const uint32_t baseA_off = (uint32_t)(m_base + (lid & 15)) * 128u + (uint32_t)(lid >> 4) * 16u;
    const uint32_t baseB_off = (uint32_t)(n_base + ((lid >> 4) << 3) + (lid & 7)) * 128u +
                               (uint32_t)((lid >> 3) & 1) * 16u;

    load_tile(0, 0);
    load_tile(1, 1);

    for (int kt = 0; kt < NKT; kt++) {
        const int stage = kt % STAGES;
        if (kt < NKT - 2) asm volatile("cp.async.wait_group 1;" ::: "memory");
        else              asm volatile("cp.async.wait_group 0;" ::: "memory");
        __syncthreads();

        if (kt + 2 < NKT) load_tile(kt + 2, (kt + 2) % STAGES);

        const uint32_t sA = tiles + stage * STAGE_BYTES;
        const uint32_t sB = sA + BM * 128;

#pragma unroll
        for (int ks = 0; ks < 4; ks++) {
            uint32_t a[4][4];
#pragma unroll
            for (int mi = 0; mi < 4; mi++) {
                uint32_t off = baseA_off + (uint32_t)mi * 2048u + (uint32_t)ks * 32u;
                uint32_t addr = sA + (off ^ ((off >> 3) & 0x70));
                asm volatile("ldmatrix.sync.aligned.m8n8.x4.shared.b16 {%0,%1,%2,%3}, [%4];"
                             : "=r"(a[mi][0]), "=r"(a[mi][1]), "=r"(a[mi][2]), "=r"(a[mi][3])
                             : "r"(addr));
            }
            uint32_t b[2][4];
#pragma unroll
            for (int nj = 0; nj < 2; nj++) {
                uint32_t off = baseB_off + (uint32_t)nj * 2048u + (uint32_t)ks * 32u;
                uint32_t addr = sB + (off ^ ((off >> 3) & 0x70));
                asm volatile("ldmatrix.sync.aligned.m8n8.x4.shared.b16 {%0,%1,%2,%3}, [%4];"
                             : "=r"(b[nj][0]), "=r"(b[nj][1]), "=r"(b[nj][2]), "=r"(b[nj][3])
                             : "r"(addr));
            }
#pragma unroll
            for (int mi = 0; mi < 4; mi++) {
#pragma unroll
                for (int n8 = 0; n8 < 4; n8++) {
                    uint32_t b0 = b[n8 >> 1][(n8 & 1) * 2 + 0];
                    uint32_t b1 = b[n8 >> 1][(n8 & 1) * 2 + 1];
                    asm volatile(
                        "mma.sync.aligned.m16n8k16.row.col.f32.f16.f16.f32 "
                        "{%0,%1,%2,%3}, {%4,%5,%6,%7}, {%8,%9}, {%0,%1,%2,%3};"
                        : "+f"(acc[mi][n8][0]), "+f"(acc[mi][n8][1]),
                          "+f"(acc[mi][n8][2]), "+f"(acc[mi][n8][3])
                        : "r"(a[mi][0]), "r"(a[mi][1]), "r"(a[mi][2]), "r"(a[mi][3]),
                          "r"(b0), "r"(b1));
                }
            }
        }
    }

    const int tg = lid >> 2;
    const int tc = (lid & 3) * 2;
    float* obase = out + (size_t)(mt * BM + m_base) * NDIM + nt * BN + n_base;
#pragma unroll
    for (int mi = 0; mi < 4; mi++) {
#pragma unroll
        for (int n8 = 0; n8 < 4; n8++) {
            int r0 = mi * 16 + tg;
            int c0 = n8 * 8 + tc;
            float2 v0 = make_float2(acc[mi][n8][0], acc[mi][n8][1]);
            float2 v1 = make_float2(acc[mi][n8][2], acc[mi][n8][3]);
            *(float2*)(obase + (size_t)r0 * NDIM + c0) = v0;
            *(float2*)(obase + (size_t)(r0 + 8) * NDIM + c0) = v1;
        }
    }
#endif
}

// ---------------------------------------------------------------------------
// Launch
// ---------------------------------------------------------------------------
typedef CUresult (*PFN_tmEncode)(
    CUtensorMap*, CUtensorMapDataType, cuuint32_t, void*,
    const cuuint64_t*, const cuuint64_t*, const cuuint32_t*, const cuuint32_t*,
    CUtensorMapInterleave, CUtensorMapSwizzle, CUtensorMapL2promotion,
    CUtensorMapFloatOOBfill);

extern "C" void kernel_launch(void* const* d_in, const int* in_sizes, int n_in,
                              void* d_out, int out_size) {
    const float* x = (const float*)d_in[0];
    const float* w = (const float*)d_in[1];
    const void* mask = d_in[2];
    float* out = (float*)d_out;

    // Device addresses of the staging globals.
    void* pA = nullptr;
    void* pB = nullptr;
    cudaGetSymbolAddress(&pA, g_A);
    cudaGetSymbolAddress(&pB, g_B);

    // Fetch cuTensorMapEncodeTiled via the runtime (no -lcuda needed).
    void* fn = nullptr;
    cudaDriverEntryPointQueryResult qres;
    cudaGetDriverEntryPoint("cuTensorMapEncodeTiled", &fn,
                            cudaEnableDefault, &qres);
    PFN_tmEncode tmEncode = (PFN_tmEncode)fn;

    CUtensorMap tmA, tmB;
    {
        cuuint64_t dims[2] = {(cuuint64_t)KDIM, (cuuint64_t)MDIM};
        cuuint64_t strides[1] = {(cuuint64_t)KDIM * 2};
        cuuint32_t box[2] = {(cuuint32_t)BK, (cuuint32_t)BM};
        cuuint32_t estr[2] = {1, 1};
        tmEncode(&tmA, CU_TENSOR_MAP_DATA_TYPE_FLOAT16, 2, pA,
                 dims, strides, box, estr,
                 CU_TENSOR_MAP_INTERLEAVE_NONE, CU_TENSOR_MAP_SWIZZLE_128B,
                 CU_TENSOR_MAP_L2_PROMOTION_L2_128B,
                 CU_TENSOR_MAP_FLOAT_OOB_FILL_NONE);
    }
    {
        cuuint64_t dims[2] = {(cuuint64_t)KDIM, (cuuint64_t)NDIM};
        cuuint64_t strides[1] = {(cuuint64_t)KDIM * 2};
        cuuint32_t box[2] = {(cuuint32_t)BK, (cuuint32_t)BN};
        cuuint32_t estr[2] = {1, 1};
        tmEncode(&tmB, CU_TENSOR_MAP_DATA_TYPE_FLOAT16, 2, pB,
                 dims, strides, box, estr,
                 CU_TENSOR_MAP_INTERLEAVE_NONE, CU_TENSOR_MAP_SWIZZLE_128B,
                 CU_TENSOR_MAP_L2_PROMOTION_L2_128B,
                 CU_TENSOR_MAP_FLOAT_OOB_FILL_NONE);
    }

    cudaFuncSetAttribute(sparse_gemm_kernel,
                         cudaFuncAttributeMaxDynamicSharedMemorySize,
                         SMEM_DYN_BYTES);

    detect_mask_kernel<<<1, 256>>>((const uint4*)mask);
    convert_x_kernel<<<4096, 256>>>(x);
    convert_w_kernel<<<2048, 256>>>(w, mask);

    dim3 grid(NDIM / BN, MDIM / BM);  // (32, 64)
    sparse_gemm_kernel<<<grid, THREADS, SMEM_DYN_BYTES>>>(out, tmA, tmB);
}

// round 10
// speedup vs baseline: 1.1702x; 1.1023x over previous
#include <cuda_runtime.h>
#include <cuda.h>
#include <cuda_fp16.h>
#include <cstdint>

// ============================================================================
// SparseLinear: out[8192,4096] = x[8192,4096] @ (weight*mask)[4096,4096]^T
// fp16 staging + tcgen05 kind::f16 GEMM (sm_103a cubin pass), fp32 TMEM acc.
//
// R10: R9 hit the TMA/L2->SMEM delivery ceiling (~17 TB/s) at 128x128 tiles.
// Quadruple arithmetic intensity: 256x256 CTA tile (M=256 as two M=128 MMA
// halves -> 2 TMEM D regions, 512 cols total; N=256 idesc). Traffic 4.29GB
// -> 2.15GB. 3 TMA stages x 64KB = 192KB smem, 1 CTA/SM, single-elected-
// thread mainloop (no CTA syncs needed).
// ============================================================================

#define MDIM 8192
#define NDIM 4096
#define KDIM 4096
#define BM 256
#define BN 256
#define BK 64
#define NKT (KDIM / BK)   // 64
#define THREADS 256
#define STAGES 3

__device__ __align__(1024) __half g_A[(size_t)MDIM * KDIM];  // x as fp16
__device__ __align__(1024) __half g_B[(size_t)NDIM * KDIM];  // (w*mask) as fp16
__device__ int g_mask_mode;  // 0 = uint8, 1 = int32, 2 = float32

// ---------------------------------------------------------------------------
// Helpers
// ---------------------------------------------------------------------------
__device__ __forceinline__ uint32_t smem_u32(const void* p) {
    uint32_t a;
    asm("{ .reg .u64 t; cvta.to.shared.u64 t, %1; cvt.u32.u64 %0, t; }"
        : "=r"(a) : "l"(p));
    return a;
}

// ---------------------------------------------------------------------------
// Mask dtype detection: coalesced uint4 scan of first 64KB.
// ---------------------------------------------------------------------------
__global__ void detect_mask_kernel(const uint4* __restrict__ m) {
    __shared__ int cnt[4];
    if (threadIdx.x < 4) cnt[threadIdx.x] = 0;
    __syncthreads();
    int local[4] = {0, 0, 0, 0};
#pragma unroll
    for (int i = 0; i < 16; i++) {
        uint4 v = m[threadIdx.x + i * 256];
        uint32_t ws[4] = {v.x, v.y, v.z, v.w};
#pragma unroll
        for (int q = 0; q < 4; q++) {
#pragma unroll
            for (int bpos = 0; bpos < 4; bpos++)
                local[bpos] += ((ws[q] >> (8 * bpos)) & 0xFF) ? 1 : 0;
        }
    }
#pragma unroll
    for (int j = 0; j < 4; j++)
        if (local[j]) atomicAdd(&cnt[j], local[j]);
    __syncthreads();
    if (threadIdx.x == 0) {
        int mode;
        if (cnt[1] == 0 && cnt[2] == 0 && cnt[3] == 0) mode = 1;       // int32
        else if (cnt[0] == 0 && cnt[1] == 0)          mode = 2;       // float32
        else                                           mode = 0;       // uint8
        g_mask_mode = mode;
    }
}

// ---------------------------------------------------------------------------
// Prep: f32 -> fp16 conversions
// ---------------------------------------------------------------------------
__global__ void convert_x_kernel(const float* __restrict__ x) {
    const size_t n4 = (size_t)MDIM * KDIM / 4;
    const float4* x4 = (const float4*)x;
    __half2* o = (__half2*)g_A;
    size_t stride = (size_t)gridDim.x * blockDim.x;
    for (size_t j = (size_t)blockIdx.x * blockDim.x + threadIdx.x; j < n4; j += stride) {
        float4 v = x4[j];
        o[2 * j + 0] = __floats2half2_rn(v.x, v.y);
        o[2 * j + 1] = __floats2half2_rn(v.z, v.w);
    }
}

__global__ void convert_w_kernel(const float* __restrict__ w,
                                 const void* __restrict__ mask) {
    const size_t n4 = (size_t)NDIM * KDIM / 4;
    const float4* w4 = (const float4*)w;
    __half2* o = (__half2*)g_B;
    const int mode = g_mask_mode;
    size_t stride = (size_t)gridDim.x * blockDim.x;
    for (size_t j = (size_t)blockIdx.x * blockDim.x + threadIdx.x; j < n4; j += stride) {
        float4 v = w4[j];
        bool k0, k1, k2, k3;
        if (mode == 0) {
            uchar4 m = ((const uchar4*)mask)[j];
            k0 = m.x; k1 = m.y; k2 = m.z; k3 = m.w;
        } else if (mode == 1) {
            int4 m = ((const int4*)mask)[j];
            k0 = m.x; k1 = m.y; k2 = m.z; k3 = m.w;
        } else {
            float4 m = ((const float4*)mask)[j];
            k0 = m.x != 0.f; k1 = m.y != 0.f; k2 = m.z != 0.f; k3 = m.w != 0.f;
        }
        float a = k0 ? v.x : 0.0f;
        float b = k1 ? v.y : 0.0f;
        float c = k2 ? v.z : 0.0f;
        float d = k3 ? v.w : 0.0f;
        o[2 * j + 0] = __floats2half2_rn(a, b);
        o[2 * j + 1] = __floats2half2_rn(c, d);
    }
}

// ---------------------------------------------------------------------------
// tcgen05-only helpers (compiled on the sm_103a cubin pass)
// ---------------------------------------------------------------------------
#if defined(__CUDA_ARCH_FEAT_SM103_ALL)
__device__ __forceinline__ bool elect_one() {
    uint32_t p;
    asm volatile(
        "{\n\t.reg .pred p;\n\t"
        "elect.sync _|p, 0xFFFFFFFF;\n\t"
        "selp.b32 %0, 1, 0, p;\n\t}"
        : "=r"(p));
    return p != 0;
}
__device__ __forceinline__ void mbar_init(uint32_t mbar, uint32_t cnt) {
    asm volatile("mbarrier.init.shared.b64 [%0], %1;" :: "r"(mbar), "r"(cnt) : "memory");
}
__device__ __forceinline__ void mbar_wait(uint32_t mbar, uint32_t parity) {
    asm volatile(
        "{\n\t.reg .pred P1;\n\t"
        "WAIT_%=:\n\t"
        "mbarrier.try_wait.parity.acquire.cta.shared::cta.b64 P1, [%0], %1, 0x989680;\n\t"
        "@P1 bra.uni DONE_%=;\n\t"
        "bra.uni WAIT_%=;\n\t"
        "DONE_%=:\n\t}"
        :: "r"(mbar), "r"(parity) : "memory");
}
__device__ __forceinline__ void mbar_expect_tx(uint32_t mbar, uint32_t bytes) {
    asm volatile("mbarrier.arrive.expect_tx.shared.b64 _, [%0], %1;"
                 :: "r"(mbar), "r"(bytes) : "memory");
}
__device__ __forceinline__ void tma_load_2d(uint32_t smem, const void* tm,
                                            int32_t x, int32_t y, uint32_t mbar) {
    asm volatile(
        "cp.async.bulk.tensor.2d.shared::cta.global.tile.mbarrier::complete_tx::bytes "
        "[%0], [%1, {%2, %3}], [%4];"
        :: "r"(smem), "l"(tm), "r"(x), "r"(y), "r"(mbar) : "memory");
}
__device__ __forceinline__ uint64_t make_desc_sw128(uint32_t addr) {
    uint64_t d = (uint64_t(2) << 61) | (uint64_t(1) << 46) |
                 (uint64_t(64) << 32) | (uint64_t(1) << 16);
    return d | ((uint64_t)(addr >> 4) & 0x3FFF);
}
// idesc: dtype=F32, f16 inputs, N=256, M=128 per dispatch
#define MMA_IDESC ((1u << 4) | ((BN / 8) << 17) | ((128 / 16) << 24))
#endif

// ---------------------------------------------------------------------------
// GEMM kernel: D[M,N] = A[M,K] @ B[N,K]^T
// ---------------------------------------------------------------------------
#define A_STAGE_BYTES (BM * 128)                       // 32KB
#define B_STAGE_BYTES (BN * 128)                       // 32KB
#define STAGE_BYTES (A_STAGE_BYTES + B_STAGE_BYTES)    // 64KB
#define SMEM_DYN_BYTES (STAGES * STAGE_BYTES + 1024)   // ~193KB

__global__ void __launch_bounds__(THREADS)
sparse_gemm_kernel(float* __restrict__ out,
                   const __grid_constant__ CUtensorMap tmA,
                   const __grid_constant__ CUtensorMap tmB) {
    extern __shared__ char dsmem[];
    const int tid = threadIdx.x;
    const int wid = tid >> 5;
    const int lid = tid & 31;
    const int nt = blockIdx.x;   // N tile (16)
    const int mt = blockIdx.y;   // M tile (32)

    const uint32_t tiles = (smem_u32(dsmem) + 1023u) & ~1023u;

#if defined(__CUDA_ARCH_FEAT_SM103_ALL)
    // ======================= tcgen05 + TMA path (sm_103a cubin) ============
    __shared__ uint64_t s_full[STAGES];   // TMA completion (expect_tx)
    __shared__ uint64_t s_mma[STAGES];    // MMA completion (commit)
    __shared__ uint32_t s_tmem_ptr;

    if (wid == 0) {
        asm volatile("tcgen05.alloc.cta_group::1.sync.aligned.shared::cta.b32 [%0], %1;"
                     :: "r"(smem_u32(&s_tmem_ptr)), "r"(512) : "memory");
        asm volatile("tcgen05.relinquish_alloc_permit.cta_group::1.sync.aligned;");
    }
    if (tid == 0) {
#pragma unroll
        for (int s = 0; s < STAGES; s++) {
            mbar_init(smem_u32(&s_full[s]), 1);
            mbar_init(smem_u32(&s_mma[s]), 1);
        }
        asm volatile("fence.proxy.async.shared::cta;" ::: "memory");
    }
    __syncthreads();

    uint32_t tmem;
    asm volatile("ld.shared.b32 %0, [%1];" : "=r"(tmem) : "r"(smem_u32(&s_tmem_ptr)));
    const uint32_t d0 = tmem;            // D rows [0,128)   cols [0,256)
    const uint32_t d1 = tmem + 256;      // D rows [128,256) cols [256,512)

    if (wid == 0 && elect_one()) {
        // Prologue: TMA tiles 0, 1.
#pragma unroll
        for (int p = 0; p < 2; p++) {
            const uint32_t sb = tiles + p * STAGE_BYTES;
            mbar_expect_tx(smem_u32(&s_full[p]), STAGE_BYTES);
            tma_load_2d(sb, &tmA, p * BK, mt * BM, smem_u32(&s_full[p]));
            tma_load_2d(sb + A_STAGE_BYTES, &tmB, p * BK, nt * BN,
                        smem_u32(&s_full[p]));
        }

        for (int kt = 0; kt < NKT; kt++) {
            const int s = kt % STAGES;

            // 1) Tile kt's TMA done.
            mbar_wait(smem_u32(&s_full[s]), (uint32_t)(kt / STAGES) & 1u);

            // 2) Issue MMAs for both M-halves (independent D chains).
            const uint32_t stage_base = tiles + s * STAGE_BYTES;
            uint64_t ad = make_desc_sw128(stage_base);              // A rows 0-127
            uint64_t ad2 = make_desc_sw128(stage_base + 128 * 128); // A rows 128-255
            uint64_t bd = make_desc_sw128(stage_base + A_STAGE_BYTES);
#pragma unroll
            for (int s4 = 0; s4 < 4; s4++) {
                uint32_t en = !(kt == 0 && s4 == 0);
                asm volatile(
                    "{\n\t.reg .pred p;\n\t"
                    "setp.ne.u32 p, %4, 0;\n\t"
                    "tcgen05.mma.cta_group::1.kind::f16 [%0], %1, %2, %3, {%5,%5,%5,%5}, p;\n\t}"
                    :: "r"(d0), "l"(ad + 2 * s4), "l"(bd + 2 * s4),
                       "r"(MMA_IDESC), "r"(en), "r"(0u) : "memory");
                asm volatile(
                    "{\n\t.reg .pred p;\n\t"
                    "setp.ne.u32 p, %4, 0;\n\t"
                    "tcgen05.mma.cta_group::1.kind::f16 [%0], %1, %2, %3, {%5,%5,%5,%5}, p;\n\t}"
                    :: "r"(d1), "l"(ad2 + 2 * s4), "l"(bd + 2 * s4),
                       "r"(MMA_IDESC), "r"(en), "r"(0u) : "memory");
            }
            asm volatile(
                "tcgen05.commit.cta_group::1.mbarrier::arrive::one.shared::cluster.b64 [%0];"
                :: "r"(smem_u32(&s_mma[s])) : "memory");

            // 3) Prefetch tile kt+2 (stage reused by MMA(kt-1): wait it).
            if (kt + 2 < NKT) {
                const int st = (kt + 2) % STAGES;
                if (kt >= 1)
                    mbar_wait(smem_u32(&s_mma[(kt - 1) % STAGES]),
                              (uint32_t)((kt - 1) / STAGES) & 1u);
                const uint32_t sb = tiles + st * STAGE_BYTES;
                mbar_expect_tx(smem_u32(&s_full[st]), STAGE_BYTES);
                tma_load_2d(sb, &tmA, (kt + 2) * BK, mt * BM, smem_u32(&s_full[st]));
                tma_load_2d(sb + A_STAGE_BYTES, &tmB, (kt + 2) * BK, nt * BN,
                            smem_u32(&s_full[st]));
            }
        }

        // Final MMA completion.
        mbar_wait(smem_u32(&s_mma[(NKT - 1) % STAGES]),
                  (uint32_t)((NKT - 1) / STAGES) & 1u);
    }

    __syncthreads();
    asm volatile("tcgen05.fence::after_thread_sync;" ::: "memory");

    // Epilogue: warps 0-3 read D0 (rows 0-127), warps 4-7 read D1 (rows 128-255).
    {
        const int h = wid >> 2;              // M half
        const int sw = wid & 3;              // subwarp row group
        const uint32_t dbase = tmem + h * 256;
        const int m = mt * BM + h * 128 + sw * 32 + lid;
        float* orow = out + (size_t)m * NDIM + nt * BN;
        uint32_t r[32];
#pragma unroll
        for (int c4 = 0; c4 < 8; c4++) {
            asm volatile(
                "tcgen05.ld.sync.aligned.32x32b.x32.b32 "
                "{%0,%1,%2,%3,%4,%5,%6,%7,%8,%9,%10,%11,%12,%13,%14,%15,"
                "%16,%17,%18,%19,%20,%21,%22,%23,%24,%25,%26,%27,%28,%29,%30,%31}, [%32];"
                : "=r"(r[0]), "=r"(r[1]), "=r"(r[2]), "=r"(r[3]),
                  "=r"(r[4]), "=r"(r[5]), "=r"(r[6]), "=r"(r[7]),
                  "=r"(r[8]), "=r"(r[9]), "=r"(r[10]), "=r"(r[11]),
                  "=r"(r[12]), "=r"(r[13]), "=r"(r[14]), "=r"(r[15]),
                  "=r"(r[16]), "=r"(r[17]), "=r"(r[18]), "=r"(r[19]),
                  "=r"(r[20]), "=r"(r[21]), "=r"(r[22]), "=r"(r[23]),
                  "=r"(r[24]), "=r"(r[25]), "=r"(r[26]), "=r"(r[27]),
                  "=r"(r[28]), "=r"(r[29]), "=r"(r[30]), "=r"(r[31])
                : "r"(dbase + c4 * 32));
            asm volatile("tcgen05.wait::ld.sync.aligned;" ::: "memory");
            float4* p = (float4*)(orow + c4 * 32);
#pragma unroll
            for (int q = 0; q < 8; q++)
                p[q] = make_float4(__uint_as_float(r[4 * q + 0]),
                                   __uint_as_float(r[4 * q + 1]),
                                   __uint_as_float(r[4 * q + 2]),
                                   __uint_as_float(r[4 * q + 3]));
        }
        asm volatile("tcgen05.fence::before_thread_sync;" ::: "memory");
    }
    __syncthreads();
    if (wid == 0)
        asm volatile("tcgen05.dealloc.cta_group::1.sync.aligned.b32 %0, %1;"
                     :: "r"(tmem), "r"(512));

#else
    // ===== fallback (compute_103 PTX pass only; cubin path always used) ====
    // Trivially correct scalar loop; never executes on sm_103a hardware.
    (void)tiles;
    for (int idx = tid; idx < BM * BN; idx += THREADS) {
        int r = idx / BN, c = idx % BN;
        const __half* a = g_A + (size_t)(mt * BM + r) * KDIM;
        const __half* b = g_B + (size_t)(nt * BN + c) * KDIM;
        float s = 0.0f;
        for (int k = 0; k < KDIM; k++)
            s += __half2float(a[k]) * __half2float(b[k]);
        out[(size_t)(mt * BM + r) * NDIM + nt * BN + c] = s;
    }
#endif
}

// ---------------------------------------------------------------------------
// Launch
// ---------------------------------------------------------------------------
typedef CUresult (*PFN_tmEncode)(
    CUtensorMap*, CUtensorMapDataType, cuuint32_t, void*,
    const cuuint64_t*, const cuuint64_t*, const cuuint32_t*, const cuuint32_t*,
    CUtensorMapInterleave, CUtensorMapSwizzle, CUtensorMapL2promotion,
    CUtensorMapFloatOOBfill);

extern "C" void kernel_launch(void* const* d_in, const int* in_sizes, int n_in,
                              void* d_out, int out_size) {
    const float* x = (const float*)d_in[0];
    const float* w = (const float*)d_in[1];
    const void* mask = d_in[2];
    float* out = (float*)d_out;

    void* pA = nullptr;
    void* pB = nullptr;
    cudaGetSymbolAddress(&pA, g_A);
    cudaGetSymbolAddress(&pB, g_B);

    void* fn = nullptr;
    cudaDriverEntryPointQueryResult qres;
    cudaGetDriverEntryPoint("cuTensorMapEncodeTiled", &fn,
                            cudaEnableDefault, &qres);
    PFN_tmEncode tmEncode = (PFN_tmEncode)fn;

    CUtensorMap tmA, tmB;
    {
        cuuint64_t dims[2] = {(cuuint64_t)KDIM, (cuuint64_t)MDIM};
        cuuint64_t strides[1] = {(cuuint64_t)KDIM * 2};
        cuuint32_t box[2] = {(cuuint32_t)BK, (cuuint32_t)BM};   // 64 x 256
        cuuint32_t estr[2] = {1, 1};
        tmEncode(&tmA, CU_TENSOR_MAP_DATA_TYPE_FLOAT16, 2, pA,
                 dims, strides, box, estr,
                 CU_TENSOR_MAP_INTERLEAVE_NONE, CU_TENSOR_MAP_SWIZZLE_128B,
                 CU_TENSOR_MAP_L2_PROMOTION_L2_128B,
                 CU_TENSOR_MAP_FLOAT_OOB_FILL_NONE);
    }
    {
        cuuint64_t dims[2] = {(cuuint64_t)KDIM, (cuuint64_t)NDIM};
        cuuint64_t strides[1] = {(cuuint64_t)KDIM * 2};
        cuuint32_t box[2] = {(cuuint32_t)BK, (cuuint32_t)BN};   // 64 x 256
        cuuint32_t estr[2] = {1, 1};
        tmEncode(&tmB, CU_TENSOR_MAP_DATA_TYPE_FLOAT16, 2, pB,
                 dims, strides, box, estr,
                 CU_TENSOR_MAP_INTERLEAVE_NONE, CU_TENSOR_MAP_SWIZZLE_128B,
                 CU_TENSOR_MAP_L2_PROMOTION_L2_128B,
                 CU_TENSOR_MAP_FLOAT_OOB_FILL_NONE);
    }

    cudaFuncSetAttribute(sparse_gemm_kernel,
                         cudaFuncAttributeMaxDynamicSharedMemorySize,
                         SMEM_DYN_BYTES);

    detect_mask_kernel<<<1, 256>>>((const uint4*)mask);
    convert_x_kernel<<<4096, 256>>>(x);
    convert_w_kernel<<<2048, 256>>>(w, mask);

    dim3 grid(NDIM / BN, MDIM / BM);  // (16, 32) = 512 CTAs
    sparse_gemm_kernel<<<grid, THREADS, SMEM_DYN_BYTES>>>(out, tmA, tmB);
}

// round 11
// speedup vs baseline: 1.1788x; 1.0073x over previous
#include <cuda_runtime.h>
#include <cuda.h>
#include <cuda_fp16.h>
#include <cstdint>

// ============================================================================
// SparseLinear: out[8192,4096] = x[8192,4096] @ (weight*mask)[4096,4096]^T
// fp16 staging + tcgen05 kind::f16 GEMM (sm_103a cubin pass), fp32 TMEM acc.
//
// R11: persistent CTAs (grid = nSM), static tile striding. Global pipeline
// index g = it*64+kt keeps the 3-stage TMA pipeline continuous ACROSS tiles
// (prefetch at kt=62/63 targets the next tile's k=0/1), removing the 4-wave
// quantization tail and per-wave pipeline refills that held R10 at 220us.
// ============================================================================

#define MDIM 8192
#define NDIM 4096
#define KDIM 4096
#define BM 256
#define BN 256
#define BK 64
#define NKT (KDIM / BK)   // 64
#define NT_TILES (NDIM / BN)              // 16
#define MT_TILES (MDIM / BM)              // 32
#define NTILES (NT_TILES * MT_TILES)      // 512
#define THREADS 256
#define STAGES 3

__device__ __align__(1024) __half g_A[(size_t)MDIM * KDIM];  // x as fp16
__device__ __align__(1024) __half g_B[(size_t)NDIM * KDIM];  // (w*mask) as fp16
__device__ int g_mask_mode;  // 0 = uint8, 1 = int32, 2 = float32

// ---------------------------------------------------------------------------
// Helpers
// ---------------------------------------------------------------------------
__device__ __forceinline__ uint32_t smem_u32(const void* p) {
    uint32_t a;
    asm("{ .reg .u64 t; cvta.to.shared.u64 t, %1; cvt.u32.u64 %0, t; }"
        : "=r"(a) : "l"(p));
    return a;
}

// ---------------------------------------------------------------------------
// Mask dtype detection: coalesced uint4 scan of first 64KB.
// ---------------------------------------------------------------------------
__global__ void detect_mask_kernel(const uint4* __restrict__ m) {
    __shared__ int cnt[4];
    if (threadIdx.x < 4) cnt[threadIdx.x] = 0;
    __syncthreads();
    int local[4] = {0, 0, 0, 0};
#pragma unroll
    for (int i = 0; i < 16; i++) {
        uint4 v = m[threadIdx.x + i * 256];
        uint32_t ws[4] = {v.x, v.y, v.z, v.w};
#pragma unroll
        for (int q = 0; q < 4; q++) {
#pragma unroll
            for (int bpos = 0; bpos < 4; bpos++)
                local[bpos] += ((ws[q] >> (8 * bpos)) & 0xFF) ? 1 : 0;
        }
    }
#pragma unroll
    for (int j = 0; j < 4; j++)
        if (local[j]) atomicAdd(&cnt[j], local[j]);
    __syncthreads();
    if (threadIdx.x == 0) {
        int mode;
        if (cnt[1] == 0 && cnt[2] == 0 && cnt[3] == 0) mode = 1;       // int32
        else if (cnt[0] == 0 && cnt[1] == 0)          mode = 2;       // float32
        else                                           mode = 0;       // uint8
        g_mask_mode = mode;
    }
}

// ---------------------------------------------------------------------------
// Prep: f32 -> fp16 conversions
// ---------------------------------------------------------------------------
__global__ void convert_x_kernel(const float* __restrict__ x) {
    const size_t n4 = (size_t)MDIM * KDIM / 4;
    const float4* x4 = (const float4*)x;
    __half2* o = (__half2*)g_A;
    size_t stride = (size_t)gridDim.x * blockDim.x;
    for (size_t j = (size_t)blockIdx.x * blockDim.x + threadIdx.x; j < n4; j += stride) {
        float4 v = x4[j];
        o[2 * j + 0] = __floats2half2_rn(v.x, v.y);
        o[2 * j + 1] = __floats2half2_rn(v.z, v.w);
    }
}

__global__ void convert_w_kernel(const float* __restrict__ w,
                                 const void* __restrict__ mask) {
    const size_t n4 = (size_t)NDIM * KDIM / 4;
    const float4* w4 = (const float4*)w;
    __half2* o = (__half2*)g_B;
    const int mode = g_mask_mode;
    size_t stride = (size_t)gridDim.x * blockDim.x;
    for (size_t j = (size_t)blockIdx.x * blockDim.x + threadIdx.x; j < n4; j += stride) {
        float4 v = w4[j];
        bool k0, k1, k2, k3;
        if (mode == 0) {
            uchar4 m = ((const uchar4*)mask)[j];
            k0 = m.x; k1 = m.y; k2 = m.z; k3 = m.w;
        } else if (mode == 1) {
            int4 m = ((const int4*)mask)[j];
            k0 = m.x; k1 = m.y; k2 = m.z; k3 = m.w;
        } else {
            float4 m = ((const float4*)mask)[j];
            k0 = m.x != 0.f; k1 = m.y != 0.f; k2 = m.z != 0.f; k3 = m.w != 0.f;
        }
        float a = k0 ? v.x : 0.0f;
        float b = k1 ? v.y : 0.0f;
        float c = k2 ? v.z : 0.0f;
        float d = k3 ? v.w : 0.0f;
        o[2 * j + 0] = __floats2half2_rn(a, b);
        o[2 * j + 1] = __floats2half2_rn(c, d);
    }
}

// ---------------------------------------------------------------------------
// tcgen05-only helpers (compiled on the sm_103a cubin pass)
// ---------------------------------------------------------------------------
#if defined(__CUDA_ARCH_FEAT_SM103_ALL)
__device__ __forceinline__ bool elect_one() {
    uint32_t p;
    asm volatile(
        "{\n\t.reg .pred p;\n\t"
        "elect.sync _|p, 0xFFFFFFFF;\n\t"
        "selp.b32 %0, 1, 0, p;\n\t}"
        : "=r"(p));
    return p != 0;
}
__device__ __forceinline__ void mbar_init(uint32_t mbar, uint32_t cnt) {
    asm volatile("mbarrier.init.shared.b64 [%0], %1;" :: "r"(mbar), "r"(cnt) : "memory");
}
__device__ __forceinline__ void mbar_wait(uint32_t mbar, uint32_t parity) {
    asm volatile(
        "{\n\t.reg .pred P1;\n\t"
        "WAIT_%=:\n\t"
        "mbarrier.try_wait.parity.acquire.cta.shared::cta.b64 P1, [%0], %1, 0x989680;\n\t"
        "@P1 bra.uni DONE_%=;\n\t"
        "bra.uni WAIT_%=;\n\t"
        "DONE_%=:\n\t}"
        :: "r"(mbar), "r"(parity) : "memory");
}
__device__ __forceinline__ void mbar_expect_tx(uint32_t mbar, uint32_t bytes) {
    asm volatile("mbarrier.arrive.expect_tx.shared.b64 _, [%0], %1;"
                 :: "r"(mbar), "r"(bytes) : "memory");
}
__device__ __forceinline__ void tma_load_2d(uint32_t smem, const void* tm,
                                            int32_t x, int32_t y, uint32_t mbar) {
    asm volatile(
        "cp.async.bulk.tensor.2d.shared::cta.global.tile.mbarrier::complete_tx::bytes "
        "[%0], [%1, {%2, %3}], [%4];"
        :: "r"(smem), "l"(tm), "r"(x), "r"(y), "r"(mbar) : "memory");
}
__device__ __forceinline__ uint64_t make_desc_sw128(uint32_t addr) {
    uint64_t d = (uint64_t(2) << 61) | (uint64_t(1) << 46) |
                 (uint64_t(64) << 32) | (uint64_t(1) << 16);
    return d | ((uint64_t)(addr >> 4) & 0x3FFF);
}
// idesc: dtype=F32, f16 inputs, N=256, M=128 per dispatch
#define MMA_IDESC ((1u << 4) | ((BN / 8) << 17) | ((128 / 16) << 24))
#endif

// ---------------------------------------------------------------------------
// GEMM kernel: D[M,N] = A[M,K] @ B[N,K]^T   — persistent CTAs
// ---------------------------------------------------------------------------
#define A_STAGE_BYTES (BM * 128)                       // 32KB
#define B_STAGE_BYTES (BN * 128)                       // 32KB
#define STAGE_BYTES (A_STAGE_BYTES + B_STAGE_BYTES)    // 64KB
#define SMEM_DYN_BYTES (STAGES * STAGE_BYTES + 1024)   // ~193KB

__global__ void __launch_bounds__(THREADS)
sparse_gemm_kernel(float* __restrict__ out,
                   const __grid_constant__ CUtensorMap tmA,
                   const __grid_constant__ CUtensorMap tmB) {
    extern __shared__ char dsmem[];
    const int tid = threadIdx.x;
    const int wid = tid >> 5;
    const int lid = tid & 31;

    const uint32_t tiles = (smem_u32(dsmem) + 1023u) & ~1023u;

#if defined(__CUDA_ARCH_FEAT_SM103_ALL)
    // ======================= tcgen05 + TMA path (sm_103a cubin) ============
    __shared__ uint64_t s_full[STAGES];   // TMA completion (expect_tx)
    __shared__ uint64_t s_mma[STAGES];    // MMA completion (commit)
    __shared__ uint32_t s_tmem_ptr;

    if (wid == 0) {
        asm volatile("tcgen05.alloc.cta_group::1.sync.aligned.shared::cta.b32 [%0], %1;"
                     :: "r"(smem_u32(&s_tmem_ptr)), "r"(512) : "memory");
        asm volatile("tcgen05.relinquish_alloc_permit.cta_group::1.sync.aligned;");
    }
    if (tid == 0) {
#pragma unroll
        for (int s = 0; s < STAGES; s++) {
            mbar_init(smem_u32(&s_full[s]), 1);
            mbar_init(smem_u32(&s_mma[s]), 1);
        }
        asm volatile("fence.proxy.async.shared::cta;" ::: "memory");
    }
    __syncthreads();

    uint32_t tmem;
    asm volatile("ld.shared.b32 %0, [%1];" : "=r"(tmem) : "r"(smem_u32(&s_tmem_ptr)));
    const uint32_t d0 = tmem;            // D rows [0,128)   TMEM cols [0,256)
    const uint32_t d1 = tmem + 256;      // D rows [128,256) TMEM cols [256,512)

    // Persistent tile loop. Continuous pipeline index g = it*NKT + kt.
    int it = 0;
    for (int t = blockIdx.x; t < NTILES; t += gridDim.x, it++) {
        const int mt = t / NT_TILES;
        const int nt = t % NT_TILES;
        const int t2 = t + gridDim.x;            // next tile (for prefetch)
        const int has_next = (t2 < NTILES);
        const int mt2 = has_next ? (t2 / NT_TILES) : 0;
        const int nt2 = has_next ? (t2 % NT_TILES) : 0;

        if (wid == 0 && elect_one()) {
            asm volatile("tcgen05.fence::after_thread_sync;" ::: "memory");

            if (it == 0) {
                // One-time prologue: stage tiles for g = 0, 1.
#pragma unroll
                for (int p = 0; p < 2; p++) {
                    const uint32_t sb = tiles + p * STAGE_BYTES;
                    mbar_expect_tx(smem_u32(&s_full[p]), STAGE_BYTES);
                    tma_load_2d(sb, &tmA, p * BK, mt * BM, smem_u32(&s_full[p]));
                    tma_load_2d(sb + A_STAGE_BYTES, &tmB, p * BK, nt * BN,
                                smem_u32(&s_full[p]));
                }
            }

            for (int kt = 0; kt < NKT; kt++) {
                const int g = it * NKT + kt;
                const int s = g % STAGES;

                // 1) Wait this tile's TMA.
                mbar_wait(smem_u32(&s_full[s]), (uint32_t)(g / STAGES) & 1u);

                // 2) Issue MMAs for both M-halves.
                const uint32_t stage_base = tiles + s * STAGE_BYTES;
                uint64_t ad = make_desc_sw128(stage_base);
                uint64_t ad2 = make_desc_sw128(stage_base + 128 * 128);
                uint64_t bd = make_desc_sw128(stage_base + A_STAGE_BYTES);
#pragma unroll
                for (int s4 = 0; s4 < 4; s4++) {
                    uint32_t en = !(kt == 0 && s4 == 0);
                    asm volatile(
                        "{\n\t.reg .pred p;\n\t"
                        "setp.ne.u32 p, %4, 0;\n\t"
                        "tcgen05.mma.cta_group::1.kind::f16 [%0], %1, %2, %3, {%5,%5,%5,%5}, p;\n\t}"
                        :: "r"(d0), "l"(ad + 2 * s4), "l"(bd + 2 * s4),
                           "r"(MMA_IDESC), "r"(en), "r"(0u) : "memory");
                    asm volatile(
                        "{\n\t.reg .pred p;\n\t"
                        "setp.ne.u32 p, %4, 0;\n\t"
                        "tcgen05.mma.cta_group::1.kind::f16 [%0], %1, %2, %3, {%5,%5,%5,%5}, p;\n\t}"
                        :: "r"(d1), "l"(ad2 + 2 * s4), "l"(bd + 2 * s4),
                           "r"(MMA_IDESC), "r"(en), "r"(0u) : "memory");
                }
                asm volatile(
                    "tcgen05.commit.cta_group::1.mbarrier::arrive::one.shared::cluster.b64 [%0];"
                    :: "r"(smem_u32(&s_mma[s])) : "memory");

                // 3) Prefetch pipeline slot g+2 (this tile's kt+2, or the
                //    NEXT tile's k = kt+2-NKT) — pipeline never drains.
                int pk = kt + 2;
                int pvalid, pmt, pnt, pkk;
                if (pk < NKT)       { pvalid = 1;        pmt = mt;  pnt = nt;  pkk = pk; }
                else if (has_next)  { pvalid = 1;        pmt = mt2; pnt = nt2; pkk = pk - NKT; }
                else                { pvalid = 0; pmt = 0; pnt = 0; pkk = 0; }
                if (pvalid) {
                    const int gp = g + 2;
                    const int sp = gp % STAGES;
                    if (g >= 1)
                        mbar_wait(smem_u32(&s_mma[(g - 1) % STAGES]),
                                  (uint32_t)((g - 1) / STAGES) & 1u);
                    const uint32_t sb = tiles + sp * STAGE_BYTES;
                    mbar_expect_tx(smem_u32(&s_full[sp]), STAGE_BYTES);
                    tma_load_2d(sb, &tmA, pkk * BK, pmt * BM, smem_u32(&s_full[sp]));
                    tma_load_2d(sb + A_STAGE_BYTES, &tmB, pkk * BK, pnt * BN,
                                smem_u32(&s_full[sp]));
                }
            }

            // Final MMA of this tile done (next tile's stage-0/1 TMA already
            // in flight and lands during the epilogue below).
            const int gl = it * NKT + NKT - 1;
            mbar_wait(smem_u32(&s_mma[gl % STAGES]), (uint32_t)(gl / STAGES) & 1u);
        }

        __syncthreads();
        asm volatile("tcgen05.fence::after_thread_sync;" ::: "memory");

        // Epilogue: warps 0-3 read D0 (rows 0-127), warps 4-7 D1 (rows 128-255).
        {
            const int h = wid >> 2;
            const int sw = wid & 3;
            const uint32_t dbase = tmem + h * 256;
            const int m = mt * BM + h * 128 + sw * 32 + lid;
            float* orow = out + (size_t)m * NDIM + nt * BN;
            uint32_t r[32];
#pragma unroll
            for (int c4 = 0; c4 < 8; c4++) {
                asm volatile(
                    "tcgen05.ld.sync.aligned.32x32b.x32.b32 "
                    "{%0,%1,%2,%3,%4,%5,%6,%7,%8,%9,%10,%11,%12,%13,%14,%15,"
                    "%16,%17,%18,%19,%20,%21,%22,%23,%24,%25,%26,%27,%28,%29,%30,%31}, [%32];"
                    : "=r"(r[0]), "=r"(r[1]), "=r"(r[2]), "=r"(r[3]),
                      "=r"(r[4]), "=r"(r[5]), "=r"(r[6]), "=r"(r[7]),
                      "=r"(r[8]), "=r"(r[9]), "=r"(r[10]), "=r"(r[11]),
                      "=r"(r[12]), "=r"(r[13]), "=r"(r[14]), "=r"(r[15]),
                      "=r"(r[16]), "=r"(r[17]), "=r"(r[18]), "=r"(r[19]),
                      "=r"(r[20]), "=r"(r[21]), "=r"(r[22]), "=r"(r[23]),
                      "=r"(r[24]), "=r"(r[25]), "=r"(r[26]), "=r"(r[27]),
                      "=r"(r[28]), "=r"(r[29]), "=r"(r[30]), "=r"(r[31])
                    : "r"(dbase + c4 * 32));
                asm volatile("tcgen05.wait::ld.sync.aligned;" ::: "memory");
                float4* p = (float4*)(orow + c4 * 32);
#pragma unroll
                for (int q = 0; q < 8; q++)
                    p[q] = make_float4(__uint_as_float(r[4 * q + 0]),
                                       __uint_as_float(r[4 * q + 1]),
                                       __uint_as_float(r[4 * q + 2]),
                                       __uint_as_float(r[4 * q + 3]));
            }
            asm volatile("tcgen05.fence::before_thread_sync;" ::: "memory");
        }
        __syncthreads();   // TMEM free for next tile's MMAs
    }

    if (wid == 0)
        asm volatile("tcgen05.dealloc.cta_group::1.sync.aligned.b32 %0, %1;"
                     :: "r"(tmem), "r"(512));

#else
    // ===== fallback (compute_103 PTX pass only; cubin path always used) ====
    (void)tiles;
    for (int t = blockIdx.x; t < NTILES; t += gridDim.x) {
        const int mt = t / NT_TILES;
        const int nt = t % NT_TILES;
        for (int idx = tid; idx < BM * BN; idx += THREADS) {
            int r = idx / BN, c = idx % BN;
            const __half* a = g_A + (size_t)(mt * BM + r) * KDIM;
            const __half* b = g_B + (size_t)(nt * BN + c) * KDIM;
            float s = 0.0f;
            for (int k = 0; k < KDIM; k++)
                s += __half2float(a[k]) * __half2float(b[k]);
            out[(size_t)(mt * BM + r) * NDIM + nt * BN + c] = s;
        }
    }
#endif
}

// ---------------------------------------------------------------------------
// Launch
// ---------------------------------------------------------------------------
typedef CUresult (*PFN_tmEncode)(
    CUtensorMap*, CUtensorMapDataType, cuuint32_t, void*,
    const cuuint64_t*, const cuuint64_t*, const cuuint32_t*, const cuuint32_t*,
    CUtensorMapInterleave, CUtensorMapSwizzle, CUtensorMapL2promotion,
    CUtensorMapFloatOOBfill);

extern "C" void kernel_launch(void* const* d_in, const int* in_sizes, int n_in,
                              void* d_out, int out_size) {
    const float* x = (const float*)d_in[0];
    const float* w = (const float*)d_in[1];
    const void* mask = d_in[2];
    float* out = (float*)d_out;

    void* pA = nullptr;
    void* pB = nullptr;
    cudaGetSymbolAddress(&pA, g_A);
    cudaGetSymbolAddress(&pB, g_B);

    void* fn = nullptr;
    cudaDriverEntryPointQueryResult qres;
    cudaGetDriverEntryPoint("cuTensorMapEncodeTiled", &fn,
                            cudaEnableDefault, &qres);
    PFN_tmEncode tmEncode = (PFN_tmEncode)fn;

    CUtensorMap tmA, tmB;
    {
        cuuint64_t dims[2] = {(cuuint64_t)KDIM, (cuuint64_t)MDIM};
        cuuint64_t strides[1] = {(cuuint64_t)KDIM * 2};
        cuuint32_t box[2] = {(cuuint32_t)BK, (cuuint32_t)BM};   // 64 x 256
        cuuint32_t estr[2] = {1, 1};
        tmEncode(&tmA, CU_TENSOR_MAP_DATA_TYPE_FLOAT16, 2, pA,
                 dims, strides, box, estr,
                 CU_TENSOR_MAP_INTERLEAVE_NONE, CU_TENSOR_MAP_SWIZZLE_128B,
                 CU_TENSOR_MAP_L2_PROMOTION_L2_128B,
                 CU_TENSOR_MAP_FLOAT_OOB_FILL_NONE);
    }
    {
        cuuint64_t dims[2] = {(cuuint64_t)KDIM, (cuuint64_t)NDIM};
        cuuint64_t strides[1] = {(cuuint64_t)KDIM * 2};
        cuuint32_t box[2] = {(cuuint32_t)BK, (cuuint32_t)BN};   // 64 x 256
        cuuint32_t estr[2] = {1, 1};
        tmEncode(&tmB, CU_TENSOR_MAP_DATA_TYPE_FLOAT16, 2, pB,
                 dims, strides, box, estr,
                 CU_TENSOR_MAP_INTERLEAVE_NONE, CU_TENSOR_MAP_SWIZZLE_128B,
                 CU_TENSOR_MAP_L2_PROMOTION_L2_128B,
                 CU_TENSOR_MAP_FLOAT_OOB_FILL_NONE);
    }

    cudaFuncSetAttribute(sparse_gemm_kernel,
                         cudaFuncAttributeMaxDynamicSharedMemorySize,
                         SMEM_DYN_BYTES);

    int nsm = 148;
    cudaDeviceGetAttribute(&nsm, cudaDevAttrMultiProcessorCount, 0);
    int grid = nsm < NTILES ? nsm : NTILES;

    detect_mask_kernel<<<1, 256>>>((const uint4*)mask);
    convert_x_kernel<<<4096, 256>>>(x);
    convert_w_kernel<<<2048, 256>>>(w, mask);

    sparse_gemm_kernel<<<grid, THREADS, SMEM_DYN_BYTES>>>(out, tmA, tmB);
}

// round 12
// speedup vs baseline: 1.2487x; 1.0593x over previous
#include <cuda_runtime.h>
#include <cuda.h>
#include <cuda_fp16.h>
#include <cstdint>

// ============================================================================
// SparseLinear: out[8192,4096] = x[8192,4096] @ (weight*mask)[4096,4096]^T
// fp16 staging + tcgen05 kind::f16 GEMM (sm_103a cubin pass), fp32 TMEM acc.
//
// R12: R11 was latency-pipeline-bound: p=2000cyc/iter from S*p >= lat + w
// with S=3, w=1024, lat~5000 (stage-reuse gating on mma completion). Deepen:
// BK=32 -> stage 32KB (SW64 swizzle), STAGES=7 (224KB smem). Window 7 slots
// now covers the TMA round trip: p -> ~790 (bw/lat bound), tensor% -> ~62.
// ============================================================================

#define MDIM 8192
#define NDIM 4096
#define KDIM 4096
#define BM 256
#define BN 256
#define BK 32
#define NKT (KDIM / BK)   // 128
#define NT_TILES (NDIM / BN)              // 16
#define MT_TILES (MDIM / BM)              // 32
#define NTILES (NT_TILES * MT_TILES)      // 512
#define THREADS 256
#define STAGES 7

__device__ __align__(1024) __half g_A[(size_t)MDIM * KDIM];  // x as fp16
__device__ __align__(1024) __half g_B[(size_t)NDIM * KDIM];  // (w*mask) as fp16
__device__ int g_mask_mode;  // 0 = uint8, 1 = int32, 2 = float32

// ---------------------------------------------------------------------------
// Helpers
// ---------------------------------------------------------------------------
__device__ __forceinline__ uint32_t smem_u32(const void* p) {
    uint32_t a;
    asm("{ .reg .u64 t; cvta.to.shared.u64 t, %1; cvt.u32.u64 %0, t; }"
        : "=r"(a) : "l"(p));
    return a;
}

// ---------------------------------------------------------------------------
// Mask dtype detection: coalesced uint4 scan of first 64KB.
// ---------------------------------------------------------------------------
__global__ void detect_mask_kernel(const uint4* __restrict__ m) {
    __shared__ int cnt[4];
    if (threadIdx.x < 4) cnt[threadIdx.x] = 0;
    __syncthreads();
    int local[4] = {0, 0, 0, 0};
#pragma unroll
    for (int i = 0; i < 16; i++) {
        uint4 v = m[threadIdx.x + i * 256];
        uint32_t ws[4] = {v.x, v.y, v.z, v.w};
#pragma unroll
        for (int q = 0; q < 4; q++) {
#pragma unroll
            for (int bpos = 0; bpos < 4; bpos++)
                local[bpos] += ((ws[q] >> (8 * bpos)) & 0xFF) ? 1 : 0;
        }
    }
#pragma unroll
    for (int j = 0; j < 4; j++)
        if (local[j]) atomicAdd(&cnt[j], local[j]);
    __syncthreads();
    if (threadIdx.x == 0) {
        int mode;
        if (cnt[1] == 0 && cnt[2] == 0 && cnt[3] == 0) mode = 1;       // int32
        else if (cnt[0] == 0 && cnt[1] == 0)          mode = 2;       // float32
        else                                           mode = 0;       // uint8
        g_mask_mode = mode;
    }
}

// ---------------------------------------------------------------------------
// Prep: f32 -> fp16 conversions
// ---------------------------------------------------------------------------
__global__ void convert_x_kernel(const float* __restrict__ x) {
    const size_t n4 = (size_t)MDIM * KDIM / 4;
    const float4* x4 = (const float4*)x;
    __half2* o = (__half2*)g_A;
    size_t stride = (size_t)gridDim.x * blockDim.x;
    for (size_t j = (size_t)blockIdx.x * blockDim.x + threadIdx.x; j < n4; j += stride) {
        float4 v = x4[j];
        o[2 * j + 0] = __floats2half2_rn(v.x, v.y);
        o[2 * j + 1] = __floats2half2_rn(v.z, v.w);
    }
}

__global__ void convert_w_kernel(const float* __restrict__ w,
                                 const void* __restrict__ mask) {
    const size_t n4 = (size_t)NDIM * KDIM / 4;
    const float4* w4 = (const float4*)w;
    __half2* o = (__half2*)g_B;
    const int mode = g_mask_mode;
    size_t stride = (size_t)gridDim.x * blockDim.x;
    for (size_t j = (size_t)blockIdx.x * blockDim.x + threadIdx.x; j < n4; j += stride) {
        float4 v = w4[j];
        bool k0, k1, k2, k3;
        if (mode == 0) {
            uchar4 m = ((const uchar4*)mask)[j];
            k0 = m.x; k1 = m.y; k2 = m.z; k3 = m.w;
        } else if (mode == 1) {
            int4 m = ((const int4*)mask)[j];
            k0 = m.x; k1 = m.y; k2 = m.z; k3 = m.w;
        } else {
            float4 m = ((const float4*)mask)[j];
            k0 = m.x != 0.f; k1 = m.y != 0.f; k2 = m.z != 0.f; k3 = m.w != 0.f;
        }
        float a = k0 ? v.x : 0.0f;
        float b = k1 ? v.y : 0.0f;
        float c = k2 ? v.z : 0.0f;
        float d = k3 ? v.w : 0.0f;
        o[2 * j + 0] = __floats2half2_rn(a, b);
        o[2 * j + 1] = __floats2half2_rn(c, d);
    }
}

// ---------------------------------------------------------------------------
// tcgen05-only helpers (compiled on the sm_103a cubin pass)
// ---------------------------------------------------------------------------
#if defined(__CUDA_ARCH_FEAT_SM103_ALL)
__device__ __forceinline__ bool elect_one() {
    uint32_t p;
    asm volatile(
        "{\n\t.reg .pred p;\n\t"
        "elect.sync _|p, 0xFFFFFFFF;\n\t"
        "selp.b32 %0, 1, 0, p;\n\t}"
        : "=r"(p));
    return p != 0;
}
__device__ __forceinline__ void mbar_init(uint32_t mbar, uint32_t cnt) {
    asm volatile("mbarrier.init.shared.b64 [%0], %1;" :: "r"(mbar), "r"(cnt) : "memory");
}
__device__ __forceinline__ void mbar_wait(uint32_t mbar, uint32_t parity) {
    asm volatile(
        "{\n\t.reg .pred P1;\n\t"
        "WAIT_%=:\n\t"
        "mbarrier.try_wait.parity.acquire.cta.shared::cta.b64 P1, [%0], %1, 0x989680;\n\t"
        "@P1 bra.uni DONE_%=;\n\t"
        "bra.uni WAIT_%=;\n\t"
        "DONE_%=:\n\t}"
        :: "r"(mbar), "r"(parity) : "memory");
}
__device__ __forceinline__ void mbar_expect_tx(uint32_t mbar, uint32_t bytes) {
    asm volatile("mbarrier.arrive.expect_tx.shared.b64 _, [%0], %1;"
                 :: "r"(mbar), "r"(bytes) : "memory");
}
__device__ __forceinline__ void tma_load_2d(uint32_t smem, const void* tm,
                                            int32_t x, int32_t y, uint32_t mbar) {
    asm volatile(
        "cp.async.bulk.tensor.2d.shared::cta.global.tile.mbarrier::complete_tx::bytes "
        "[%0], [%1, {%2, %3}], [%4];"
        :: "r"(smem), "l"(tm), "r"(x), "r"(y), "r"(mbar) : "memory");
}
// SW64 K-major descriptor: layout=4, version=1, SBO=32 (512B = 8 rows x 64B
// atom), LBO=1 (16B).
__device__ __forceinline__ uint64_t make_desc_sw64(uint32_t addr) {
    uint64_t d = (uint64_t(4) << 61) | (uint64_t(1) << 46) |
                 (uint64_t(32) << 32) | (uint64_t(1) << 16);
    return d | ((uint64_t)(addr >> 4) & 0x3FFF);
}
// idesc: dtype=F32, f16 inputs, N=256, M=128 per dispatch
#define MMA_IDESC ((1u << 4) | ((BN / 8) << 17) | ((128 / 16) << 24))
#endif

// ---------------------------------------------------------------------------
// GEMM kernel: D[M,N] = A[M,K] @ B[N,K]^T   — persistent CTAs, 7-stage TMA
// ---------------------------------------------------------------------------
#define A_STAGE_BYTES (BM * 64)                        // 16KB (rows of 64B)
#define B_STAGE_BYTES (BN * 64)                        // 16KB
#define STAGE_BYTES (A_STAGE_BYTES + B_STAGE_BYTES)    // 32KB
#define SMEM_DYN_BYTES (STAGES * STAGE_BYTES + 1024)   // ~225KB

__global__ void __launch_bounds__(THREADS)
sparse_gemm_kernel(float* __restrict__ out,
                   const __grid_constant__ CUtensorMap tmA,
                   const __grid_constant__ CUtensorMap tmB) {
    extern __shared__ char dsmem[];
    const int tid = threadIdx.x;
    const int wid = tid >> 5;
    const int lid = tid & 31;

    const uint32_t tiles = (smem_u32(dsmem) + 1023u) & ~1023u;

#if defined(__CUDA_ARCH_FEAT_SM103_ALL)
    // ======================= tcgen05 + TMA path (sm_103a cubin) ============
    __shared__ uint64_t s_full[STAGES];   // TMA completion (expect_tx)
    __shared__ uint64_t s_mma[STAGES];    // MMA completion (commit)
    __shared__ uint32_t s_tmem_ptr;

    if (wid == 0) {
        asm volatile("tcgen05.alloc.cta_group::1.sync.aligned.shared::cta.b32 [%0], %1;"
                     :: "r"(smem_u32(&s_tmem_ptr)), "r"(512) : "memory");
        asm volatile("tcgen05.relinquish_alloc_permit.cta_group::1.sync.aligned;");
    }
    if (tid == 0) {
#pragma unroll
        for (int s = 0; s < STAGES; s++) {
            mbar_init(smem_u32(&s_full[s]), 1);
            mbar_init(smem_u32(&s_mma[s]), 1);
        }
        asm volatile("fence.proxy.async.shared::cta;" ::: "memory");
    }
    __syncthreads();

    uint32_t tmem;
    asm volatile("ld.shared.b32 %0, [%1];" : "=r"(tmem) : "r"(smem_u32(&s_tmem_ptr)));
    const uint32_t d0 = tmem;            // D rows [0,128)   TMEM cols [0,256)
    const uint32_t d1 = tmem + 256;      // D rows [128,256) TMEM cols [256,512)

    // Persistent tile loop. Continuous pipeline index g = it*NKT + kt.
    int it = 0;
    for (int t = blockIdx.x; t < NTILES; t += gridDim.x, it++) {
        const int mt = t / NT_TILES;
        const int nt = t % NT_TILES;
        const int t2 = t + gridDim.x;            // next tile (for prefetch)
        const int has_next = (t2 < NTILES);
        const int mt2 = has_next ? (t2 / NT_TILES) : 0;
        const int nt2 = has_next ? (t2 % NT_TILES) : 0;

        if (wid == 0 && elect_one()) {
            asm volatile("tcgen05.fence::after_thread_sync;" ::: "memory");

            if (it == 0) {
                // One-time prologue: stage slots g = 0 .. STAGES-2.
#pragma unroll
                for (int p = 0; p < STAGES - 1; p++) {
                    const uint32_t sb = tiles + p * STAGE_BYTES;
                    mbar_expect_tx(smem_u32(&s_full[p]), STAGE_BYTES);
                    tma_load_2d(sb, &tmA, p * BK, mt * BM, smem_u32(&s_full[p]));
                    tma_load_2d(sb + A_STAGE_BYTES, &tmB, p * BK, nt * BN,
                                smem_u32(&s_full[p]));
                }
            }

            for (int kt = 0; kt < NKT; kt++) {
                const int g = it * NKT + kt;
                const int s = g % STAGES;

                // 1) Wait this slot's TMA.
                mbar_wait(smem_u32(&s_full[s]), (uint32_t)(g / STAGES) & 1u);

                // 2) Issue MMAs: 2 K-steps x 2 M-halves.
                const uint32_t stage_base = tiles + s * STAGE_BYTES;
                uint64_t ad = make_desc_sw64(stage_base);
                uint64_t ad2 = make_desc_sw64(stage_base + 128 * 64);
                uint64_t bd = make_desc_sw64(stage_base + A_STAGE_BYTES);
#pragma unroll
                for (int s4 = 0; s4 < 2; s4++) {
                    uint32_t en = !(kt == 0 && s4 == 0);
                    asm volatile(
                        "{\n\t.reg .pred p;\n\t"
                        "setp.ne.u32 p, %4, 0;\n\t"
                        "tcgen05.mma.cta_group::1.kind::f16 [%0], %1, %2, %3, {%5,%5,%5,%5}, p;\n\t}"
                        :: "r"(d0), "l"(ad + 2 * s4), "l"(bd + 2 * s4),
                           "r"(MMA_IDESC), "r"(en), "r"(0u) : "memory");
                    asm volatile(
                        "{\n\t.reg .pred p;\n\t"
                        "setp.ne.u32 p, %4, 0;\n\t"
                        "tcgen05.mma.cta_group::1.kind::f16 [%0], %1, %2, %3, {%5,%5,%5,%5}, p;\n\t}"
                        :: "r"(d1), "l"(ad2 + 2 * s4), "l"(bd + 2 * s4),
                           "r"(MMA_IDESC), "r"(en), "r"(0u) : "memory");
                }
                asm volatile(
                    "tcgen05.commit.cta_group::1.mbarrier::arrive::one.shared::cluster.b64 [%0];"
                    :: "r"(smem_u32(&s_mma[s])) : "memory");

                // 3) Prefetch slot g+(STAGES-1): stage (g-1)%S, last read by
                //    MMA(g-1) -> gate on it, then reload (continuous across
                //    tiles: pk >= NKT maps to the next tile's k).
                int pk = kt + (STAGES - 1);
                int pvalid, pmt, pnt, pkk;
                if (pk < NKT)       { pvalid = 1;        pmt = mt;  pnt = nt;  pkk = pk; }
                else if (has_next)  { pvalid = 1;        pmt = mt2; pnt = nt2; pkk = pk - NKT; }
                else                { pvalid = 0; pmt = 0; pnt = 0; pkk = 0; }
                if (pvalid) {
                    const int gp = g + (STAGES - 1);
                    const int sp = gp % STAGES;
                    if (g >= 1)
                        mbar_wait(smem_u32(&s_mma[(g - 1) % STAGES]),
                                  (uint32_t)((g - 1) / STAGES) & 1u);
                    const uint32_t sb = tiles + sp * STAGE_BYTES;
                    mbar_expect_tx(smem_u32(&s_full[sp]), STAGE_BYTES);
                    tma_load_2d(sb, &tmA, pkk * BK, pmt * BM, smem_u32(&s_full[sp]));
                    tma_load_2d(sb + A_STAGE_BYTES, &tmB, pkk * BK, pnt * BN,
                                smem_u32(&s_full[sp]));
                }
            }

            // Final MMA of this tile done (next tile's early slots already
            // in flight; they land during the epilogue below).
            const int gl = it * NKT + NKT - 1;
            mbar_wait(smem_u32(&s_mma[gl % STAGES]), (uint32_t)(gl / STAGES) & 1u);
        }

        __syncthreads();
        asm volatile("tcgen05.fence::after_thread_sync;" ::: "memory");

        // Epilogue: warps 0-3 read D0 (rows 0-127), warps 4-7 D1 (rows 128-255).
        {
            const int h = wid >> 2;
            const int sw = wid & 3;
            const uint32_t dbase = tmem + h * 256;
            const int m = mt * BM + h * 128 + sw * 32 + lid;
            float* orow = out + (size_t)m * NDIM + nt * BN;
            uint32_t r[32];
#pragma unroll
            for (int c4 = 0; c4 < 8; c4++) {
                asm volatile(
                    "tcgen05.ld.sync.aligned.32x32b.x32.b32 "
                    "{%0,%1,%2,%3,%4,%5,%6,%7,%8,%9,%10,%11,%12,%13,%14,%15,"
                    "%16,%17,%18,%19,%20,%21,%22,%23,%24,%25,%26,%27,%28,%29,%30,%31}, [%32];"
                    : "=r"(r[0]), "=r"(r[1]), "=r"(r[2]), "=r"(r[3]),
                      "=r"(r[4]), "=r"(r[5]), "=r"(r[6]), "=r"(r[7]),
                      "=r"(r[8]), "=r"(r[9]), "=r"(r[10]), "=r"(r[11]),
                      "=r"(r[12]), "=r"(r[13]), "=r"(r[14]), "=r"(r[15]),
                      "=r"(r[16]), "=r"(r[17]), "=r"(r[18]), "=r"(r[19]),
                      "=r"(r[20]), "=r"(r[21]), "=r"(r[22]), "=r"(r[23]),
                      "=r"(r[24]), "=r"(r[25]), "=r"(r[26]), "=r"(r[27]),
                      "=r"(r[28]), "=r"(r[29]), "=r"(r[30]), "=r"(r[31])
                    : "r"(dbase + c4 * 32));
                asm volatile("tcgen05.wait::ld.sync.aligned;" ::: "memory");
                float4* p = (float4*)(orow + c4 * 32);
#pragma unroll
                for (int q = 0; q < 8; q++)
                    p[q] = make_float4(__uint_as_float(r[4 * q + 0]),
                                       __uint_as_float(r[4 * q + 1]),
                                       __uint_as_float(r[4 * q + 2]),
                                       __uint_as_float(r[4 * q + 3]));
            }
            asm volatile("tcgen05.fence::before_thread_sync;" ::: "memory");
        }
        __syncthreads();   // TMEM free for next tile's MMAs
    }

    if (wid == 0)
        asm volatile("tcgen05.dealloc.cta_group::1.sync.aligned.b32 %0, %1;"
                     :: "r"(tmem), "r"(512));

#else
    // ===== fallback (compute_103 PTX pass only; cubin path always used) ====
    (void)tiles;
    for (int t = blockIdx.x; t < NTILES; t += gridDim.x) {
        const int mt = t / NT_TILES;
        const int nt = t % NT_TILES;
        for (int idx = tid; idx < BM * BN; idx += THREADS) {
            int r = idx / BN, c = idx % BN;
            const __half* a = g_A + (size_t)(mt * BM + r) * KDIM;
            const __half* b = g_B + (size_t)(nt * BN + c) * KDIM;
            float s = 0.0f;
            for (int k = 0; k < KDIM; k++)
                s += __half2float(a[k]) * __half2float(b[k]);
            out[(size_t)(mt * BM + r) * NDIM + nt * BN + c] = s;
        }
    }
#endif
}

// ---------------------------------------------------------------------------
// Launch
// ---------------------------------------------------------------------------
typedef CUresult (*PFN_tmEncode)(
    CUtensorMap*, CUtensorMapDataType, cuuint32_t, void*,
    const cuuint64_t*, const cuuint64_t*, const cuuint32_t*, const cuuint32_t*,
    CUtensorMapInterleave, CUtensorMapSwizzle, CUtensorMapL2promotion,
    CUtensorMapFloatOOBfill);

extern "C" void kernel_launch(void* const* d_in, const int* in_sizes, int n_in,
                              void* d_out, int out_size) {
    const float* x = (const float*)d_in[0];
    const float* w = (const float*)d_in[1];
    const void* mask = d_in[2];
    float* out = (float*)d_out;

    void* pA = nullptr;
    void* pB = nullptr;
    cudaGetSymbolAddress(&pA, g_A);
    cudaGetSymbolAddress(&pB, g_B);

    void* fn = nullptr;
    cudaDriverEntryPointQueryResult qres;
    cudaGetDriverEntryPoint("cuTensorMapEncodeTiled", &fn,
                            cudaEnableDefault, &qres);
    PFN_tmEncode tmEncode = (PFN_tmEncode)fn;

    CUtensorMap tmA, tmB;
    {
        cuuint64_t dims[2] = {(cuuint64_t)KDIM, (cuuint64_t)MDIM};
        cuuint64_t strides[1] = {(cuuint64_t)KDIM * 2};
        cuuint32_t box[2] = {(cuuint32_t)BK, (cuuint32_t)BM};   // 32 x 256
        cuuint32_t estr[2] = {1, 1};
        tmEncode(&tmA, CU_TENSOR_MAP_DATA_TYPE_FLOAT16, 2, pA,
                 dims, strides, box, estr,
                 CU_TENSOR_MAP_INTERLEAVE_NONE, CU_TENSOR_MAP_SWIZZLE_64B,
                 CU_TENSOR_MAP_L2_PROMOTION_L2_128B,
                 CU_TENSOR_MAP_FLOAT_OOB_FILL_NONE);
    }
    {
        cuuint64_t dims[2] = {(cuuint64_t)KDIM, (cuuint64_t)NDIM};
        cuuint64_t strides[1] = {(cuuint64_t)KDIM * 2};
        cuuint32_t box[2] = {(cuuint32_t)BK, (cuuint32_t)BN};   // 32 x 256
        cuuint32_t estr[2] = {1, 1};
        tmEncode(&tmB, CU_TENSOR_MAP_DATA_TYPE_FLOAT16, 2, pB,
                 dims, strides, box, estr,
                 CU_TENSOR_MAP_INTERLEAVE_NONE, CU_TENSOR_MAP_SWIZZLE_64B,
                 CU_TENSOR_MAP_L2_PROMOTION_L2_128B,
                 CU_TENSOR_MAP_FLOAT_OOB_FILL_NONE);
    }

    cudaFuncSetAttribute(sparse_gemm_kernel,
                         cudaFuncAttributeMaxDynamicSharedMemorySize,
                         SMEM_DYN_BYTES);

    int nsm = 148;
    cudaDeviceGetAttribute(&nsm, cudaDevAttrMultiProcessorCount, 0);
    int grid = nsm < NTILES ? nsm : NTILES;

    detect_mask_kernel<<<1, 256>>>((const uint4*)mask);
    convert_x_kernel<<<4096, 256>>>(x);
    convert_w_kernel<<<2048, 256>>>(w, mask);

    sparse_gemm_kernel<<<grid, THREADS, SMEM_DYN_BYTES>>>(out, tmA, tmB);
}

// round 13
// speedup vs baseline: 1.2521x; 1.0028x over previous
#include <cuda_runtime.h>
#include <cuda.h>
#include <cuda_fp16.h>
#include <cstdint>

// ============================================================================
// SparseLinear: out[8192,4096] = x[8192,4096] @ (weight*mask)[4096,4096]^T
// fp16 staging + tcgen05 kind::f16 GEMM (sm_103a cubin pass), fp32 TMEM acc.
//
// R13: warp specialization. R12's single elected thread serialized two ~90cyc
// mbarrier waits + MMA + TMA issue per iteration (p=735 vs 512 work). Now:
// warp 8 = flat TMA producer (gated only on stage-reuse mma barriers),
// warp 0 = MMA issuer (gated only on tile-full barriers), warps 0-7 do the
// epilogue behind a named barrier (bar.sync 1,256) the producer never joins
// -> next tile's TMA runs underneath the epilogue.
// ============================================================================

#define MDIM 8192
#define NDIM 4096
#define KDIM 4096
#define BM 256
#define BN 256
#define BK 32
#define NKT (KDIM / BK)   // 128
#define NT_TILES (NDIM / BN)              // 16
#define MT_TILES (MDIM / BM)              // 32
#define NTILES (NT_TILES * MT_TILES)      // 512
#define THREADS 288
#define STAGES 7

__device__ __align__(1024) __half g_A[(size_t)MDIM * KDIM];  // x as fp16
__device__ __align__(1024) __half g_B[(size_t)NDIM * KDIM];  // (w*mask) as fp16
__device__ int g_mask_mode;  // 0 = uint8, 1 = int32, 2 = float32

// ---------------------------------------------------------------------------
// Helpers
// ---------------------------------------------------------------------------
__device__ __forceinline__ uint32_t smem_u32(const void* p) {
    uint32_t a;
    asm("{ .reg .u64 t; cvta.to.shared.u64 t, %1; cvt.u32.u64 %0, t; }"
        : "=r"(a) : "l"(p));
    return a;
}

// ---------------------------------------------------------------------------
// Mask dtype detection: coalesced uint4 scan of first 64KB.
// ---------------------------------------------------------------------------
__global__ void detect_mask_kernel(const uint4* __restrict__ m) {
    __shared__ int cnt[4];
    if (threadIdx.x < 4) cnt[threadIdx.x] = 0;
    __syncthreads();
    int local[4] = {0, 0, 0, 0};
#pragma unroll
    for (int i = 0; i < 16; i++) {
        uint4 v = m[threadIdx.x + i * 256];
        uint32_t ws[4] = {v.x, v.y, v.z, v.w};
#pragma unroll
        for (int q = 0; q < 4; q++) {
#pragma unroll
            for (int bpos = 0; bpos < 4; bpos++)
                local[bpos] += ((ws[q] >> (8 * bpos)) & 0xFF) ? 1 : 0;
        }
    }
#pragma unroll
    for (int j = 0; j < 4; j++)
        if (local[j]) atomicAdd(&cnt[j], local[j]);
    __syncthreads();
    if (threadIdx.x == 0) {
        int mode;
        if (cnt[1] == 0 && cnt[2] == 0 && cnt[3] == 0) mode = 1;       // int32
        else if (cnt[0] == 0 && cnt[1] == 0)          mode = 2;       // float32
        else                                           mode = 0;       // uint8
        g_mask_mode = mode;
    }
}

// ---------------------------------------------------------------------------
// Prep: f32 -> fp16 conversions
// ---------------------------------------------------------------------------
__global__ void convert_x_kernel(const float* __restrict__ x) {
    const size_t n4 = (size_t)MDIM * KDIM / 4;
    const float4* x4 = (const float4*)x;
    __half2* o = (__half2*)g_A;
    size_t stride = (size_t)gridDim.x * blockDim.x;
    for (size_t j = (size_t)blockIdx.x * blockDim.x + threadIdx.x; j < n4; j += stride) {
        float4 v = x4[j];
        o[2 * j + 0] = __floats2half2_rn(v.x, v.y);
        o[2 * j + 1] = __floats2half2_rn(v.z, v.w);
    }
}

__global__ void convert_w_kernel(const float* __restrict__ w,
                                 const void* __restrict__ mask) {
    const size_t n4 = (size_t)NDIM * KDIM / 4;
    const float4* w4 = (const float4*)w;
    __half2* o = (__half2*)g_B;
    const int mode = g_mask_mode;
    size_t stride = (size_t)gridDim.x * blockDim.x;
    for (size_t j = (size_t)blockIdx.x * blockDim.x + threadIdx.x; j < n4; j += stride) {
        float4 v = w4[j];
        bool k0, k1, k2, k3;
        if (mode == 0) {
            uchar4 m = ((const uchar4*)mask)[j];
            k0 = m.x; k1 = m.y; k2 = m.z; k3 = m.w;
        } else if (mode == 1) {
            int4 m = ((const int4*)mask)[j];
            k0 = m.x; k1 = m.y; k2 = m.z; k3 = m.w;
        } else {
            float4 m = ((const float4*)mask)[j];
            k0 = m.x != 0.f; k1 = m.y != 0.f; k2 = m.z != 0.f; k3 = m.w != 0.f;
        }
        float a = k0 ? v.x : 0.0f;
        float b = k1 ? v.y : 0.0f;
        float c = k2 ? v.z : 0.0f;
        float d = k3 ? v.w : 0.0f;
        o[2 * j + 0] = __floats2half2_rn(a, b);
        o[2 * j + 1] = __floats2half2_rn(c, d);
    }
}

// ---------------------------------------------------------------------------
// tcgen05-only helpers (compiled on the sm_103a cubin pass)
// ---------------------------------------------------------------------------
#if defined(__CUDA_ARCH_FEAT_SM103_ALL)
__device__ __forceinline__ bool elect_one() {
    uint32_t p;
    asm volatile(
        "{\n\t.reg .pred p;\n\t"
        "elect.sync _|p, 0xFFFFFFFF;\n\t"
        "selp.b32 %0, 1, 0, p;\n\t}"
        : "=r"(p));
    return p != 0;
}
__device__ __forceinline__ void mbar_init(uint32_t mbar, uint32_t cnt) {
    asm volatile("mbarrier.init.shared.b64 [%0], %1;" :: "r"(mbar), "r"(cnt) : "memory");
}
__device__ __forceinline__ void mbar_wait(uint32_t mbar, uint32_t parity) {
    asm volatile(
        "{\n\t.reg .pred P1;\n\t"
        "WAIT_%=:\n\t"
        "mbarrier.try_wait.parity.acquire.cta.shared::cta.b64 P1, [%0], %1, 0x989680;\n\t"
        "@P1 bra.uni DONE_%=;\n\t"
        "bra.uni WAIT_%=;\n\t"
        "DONE_%=:\n\t}"
        :: "r"(mbar), "r"(parity) : "memory");
}
__device__ __forceinline__ void mbar_expect_tx(uint32_t mbar, uint32_t bytes) {
    asm volatile("mbarrier.arrive.expect_tx.shared.b64 _, [%0], %1;"
                 :: "r"(mbar), "r"(bytes) : "memory");
}
__device__ __forceinline__ void tma_load_2d(uint32_t smem, const void* tm,
                                            int32_t x, int32_t y, uint32_t mbar) {
    asm volatile(
        "cp.async.bulk.tensor.2d.shared::cta.global.tile.mbarrier::complete_tx::bytes "
        "[%0], [%1, {%2, %3}], [%4];"
        :: "r"(smem), "l"(tm), "r"(x), "r"(y), "r"(mbar) : "memory");
}
// SW64 K-major descriptor: layout=4, version=1, SBO=32, LBO=1.
__device__ __forceinline__ uint64_t make_desc_sw64(uint32_t addr) {
    uint64_t d = (uint64_t(4) << 61) | (uint64_t(1) << 46) |
                 (uint64_t(32) << 32) | (uint64_t(1) << 16);
    return d | ((uint64_t)(addr >> 4) & 0x3FFF);
}
// idesc: dtype=F32, f16 inputs, N=256, M=128 per dispatch
#define MMA_IDESC ((1u << 4) | ((BN / 8) << 17) | ((128 / 16) << 24))
#endif

// ---------------------------------------------------------------------------
// GEMM kernel: D[M,N] = A[M,K] @ B[N,K]^T — persistent, warp-specialized
// ---------------------------------------------------------------------------
#define A_STAGE_BYTES (BM * 64)                        // 16KB (rows of 64B)
#define B_STAGE_BYTES (BN * 64)                        // 16KB
#define STAGE_BYTES (A_STAGE_BYTES + B_STAGE_BYTES)    // 32KB
#define SMEM_DYN_BYTES (STAGES * STAGE_BYTES + 1024)   // ~225KB

__global__ void __launch_bounds__(THREADS)
sparse_gemm_kernel(float* __restrict__ out,
                   const __grid_constant__ CUtensorMap tmA,
                   const __grid_constant__ CUtensorMap tmB) {
    extern __shared__ char dsmem[];
    const int tid = threadIdx.x;
    const int wid = tid >> 5;
    const int lid = tid & 31;

    const uint32_t tiles = (smem_u32(dsmem) + 1023u) & ~1023u;

#if defined(__CUDA_ARCH_FEAT_SM103_ALL)
    // ======================= tcgen05 + TMA path (sm_103a cubin) ============
    __shared__ uint64_t s_full[STAGES];   // TMA completion (expect_tx)
    __shared__ uint64_t s_mma[STAGES];    // MMA completion (commit)
    __shared__ uint32_t s_tmem_ptr;

    if (wid == 0) {
        asm volatile("tcgen05.alloc.cta_group::1.sync.aligned.shared::cta.b32 [%0], %1;"
                     :: "r"(smem_u32(&s_tmem_ptr)), "r"(512) : "memory");
        asm volatile("tcgen05.relinquish_alloc_permit.cta_group::1.sync.aligned;");
    }
    if (tid == 0) {
#pragma unroll
        for (int s = 0; s < STAGES; s++) {
            mbar_init(smem_u32(&s_full[s]), 1);
            mbar_init(smem_u32(&s_mma[s]), 1);
        }
        asm volatile("fence.proxy.async.shared::cta;" ::: "memory");
    }
    __syncthreads();

    uint32_t tmem;
    asm volatile("ld.shared.b32 %0, [%1];" : "=r"(tmem) : "r"(smem_u32(&s_tmem_ptr)));
    const uint32_t d0 = tmem;            // D rows [0,128)   TMEM cols [0,256)
    const uint32_t d1 = tmem + 256;      // D rows [128,256) TMEM cols [256,512)

    if (wid == 8) {
        // =================== PRODUCER warp (never joins bar 1) =============
        if (elect_one()) {
            int g = 0;
            for (int t = blockIdx.x; t < NTILES; t += gridDim.x) {
                const int pmt = t / NT_TILES;
                const int pnt = t % NT_TILES;
                for (int kt = 0; kt < NKT; kt++, g++) {
                    const int s = g % STAGES;
                    // Stage s last consumed by MMA slot g-STAGES.
                    if (g >= STAGES)
                        mbar_wait(smem_u32(&s_mma[s]),
                                  (uint32_t)((g - STAGES) / STAGES) & 1u);
                    const uint32_t sb = tiles + s * STAGE_BYTES;
                    mbar_expect_tx(smem_u32(&s_full[s]), STAGE_BYTES);
                    tma_load_2d(sb, &tmA, kt * BK, pmt * BM, smem_u32(&s_full[s]));
                    tma_load_2d(sb + A_STAGE_BYTES, &tmB, kt * BK, pnt * BN,
                                smem_u32(&s_full[s]));
                }
            }
        }
    } else {
        // ============== MMA issuer (warp 0) + epilogue (warps 0-7) ========
        int it = 0;
        for (int t = blockIdx.x; t < NTILES; t += gridDim.x, it++) {
            const int mt = t / NT_TILES;
            const int nt = t % NT_TILES;

            if (wid == 0 && elect_one()) {
                asm volatile("tcgen05.fence::after_thread_sync;" ::: "memory");
                for (int kt = 0; kt < NKT; kt++) {
                    const int g = it * NKT + kt;
                    const int s = g % STAGES;
                    mbar_wait(smem_u32(&s_full[s]), (uint32_t)(g / STAGES) & 1u);

                    const uint32_t stage_base = tiles + s * STAGE_BYTES;
                    uint64_t ad = make_desc_sw64(stage_base);
                    uint64_t ad2 = make_desc_sw64(stage_base + 128 * 64);
                    uint64_t bd = make_desc_sw64(stage_base + A_STAGE_BYTES);
#pragma unroll
                    for (int s4 = 0; s4 < 2; s4++) {
                        uint32_t en = !(kt == 0 && s4 == 0);
                        asm volatile(
                            "{\n\t.reg .pred p;\n\t"
                            "setp.ne.u32 p, %4, 0;\n\t"
                            "tcgen05.mma.cta_group::1.kind::f16 [%0], %1, %2, %3, {%5,%5,%5,%5}, p;\n\t}"
                            :: "r"(d0), "l"(ad + 2 * s4), "l"(bd + 2 * s4),
                               "r"(MMA_IDESC), "r"(en), "r"(0u) : "memory");
                        asm volatile(
                            "{\n\t.reg .pred p;\n\t"
                            "setp.ne.u32 p, %4, 0;\n\t"
                            "tcgen05.mma.cta_group::1.kind::f16 [%0], %1, %2, %3, {%5,%5,%5,%5}, p;\n\t}"
                            :: "r"(d1), "l"(ad2 + 2 * s4), "l"(bd + 2 * s4),
                               "r"(MMA_IDESC), "r"(en), "r"(0u) : "memory");
                    }
                    asm volatile(
                        "tcgen05.commit.cta_group::1.mbarrier::arrive::one.shared::cluster.b64 [%0];"
                        :: "r"(smem_u32(&s_mma[s])) : "memory");
                }
                // Final MMA of this tile drained before epilogue reads TMEM.
                const int gl = it * NKT + NKT - 1;
                mbar_wait(smem_u32(&s_mma[gl % STAGES]),
                          (uint32_t)(gl / STAGES) & 1u);
            }

            // Epilogue barrier: warps 0-7 only (producer keeps streaming TMA).
            asm volatile("bar.sync 1, 256;" ::: "memory");
            asm volatile("tcgen05.fence::after_thread_sync;" ::: "memory");

            {
                const int h = wid >> 2;
                const int sw = wid & 3;
                const uint32_t dbase = tmem + h * 256;
                const int m = mt * BM + h * 128 + sw * 32 + lid;
                float* orow = out + (size_t)m * NDIM + nt * BN;
                uint32_t r[32];
#pragma unroll
                for (int c4 = 0; c4 < 8; c4++) {
                    asm volatile(
                        "tcgen05.ld.sync.aligned.32x32b.x32.b32 "
                        "{%0,%1,%2,%3,%4,%5,%6,%7,%8,%9,%10,%11,%12,%13,%14,%15,"
                        "%16,%17,%18,%19,%20,%21,%22,%23,%24,%25,%26,%27,%28,%29,%30,%31}, [%32];"
                        : "=r"(r[0]), "=r"(r[1]), "=r"(r[2]), "=r"(r[3]),
                          "=r"(r[4]), "=r"(r[5]), "=r"(r[6]), "=r"(r[7]),
                          "=r"(r[8]), "=r"(r[9]), "=r"(r[10]), "=r"(r[11]),
                          "=r"(r[12]), "=r"(r[13]), "=r"(r[14]), "=r"(r[15]),
                          "=r"(r[16]), "=r"(r[17]), "=r"(r[18]), "=r"(r[19]),
                          "=r"(r[20]), "=r"(r[21]), "=r"(r[22]), "=r"(r[23]),
                          "=r"(r[24]), "=r"(r[25]), "=r"(r[26]), "=r"(r[27]),
                          "=r"(r[28]), "=r"(r[29]), "=r"(r[30]), "=r"(r[31])
                        : "r"(dbase + c4 * 32));
                    asm volatile("tcgen05.wait::ld.sync.aligned;" ::: "memory");
                    float4* p = (float4*)(orow + c4 * 32);
#pragma unroll
                    for (int q = 0; q < 8; q++)
                        p[q] = make_float4(__uint_as_float(r[4 * q + 0]),
                                           __uint_as_float(r[4 * q + 1]),
                                           __uint_as_float(r[4 * q + 2]),
                                           __uint_as_float(r[4 * q + 3]));
                }
                asm volatile("tcgen05.fence::before_thread_sync;" ::: "memory");
            }
            // TMEM free for next tile's MMAs.
            asm volatile("bar.sync 1, 256;" ::: "memory");
        }
    }

    __syncthreads();   // all 9 warps
    if (wid == 0)
        asm volatile("tcgen05.dealloc.cta_group::1.sync.aligned.b32 %0, %1;"
                     :: "r"(tmem), "r"(512));

#else
    // ===== fallback (compute_103 PTX pass only; cubin path always used) ====
    (void)tiles;
    for (int t = blockIdx.x; t < NTILES; t += gridDim.x) {
        const int mt = t / NT_TILES;
        const int nt = t % NT_TILES;
        for (int idx = tid; idx < BM * BN; idx += THREADS) {
            int r = idx / BN, c = idx % BN;
            const __half* a = g_A + (size_t)(mt * BM + r) * KDIM;
            const __half* b = g_B + (size_t)(nt * BN + c) * KDIM;
            float s = 0.0f;
            for (int k = 0; k < KDIM; k++)
                s += __half2float(a[k]) * __half2float(b[k]);
            out[(size_t)(mt * BM + r) * NDIM + nt * BN + c] = s;
        }
    }
#endif
}

// ---------------------------------------------------------------------------
// Launch
// ---------------------------------------------------------------------------
typedef CUresult (*PFN_tmEncode)(
    CUtensorMap*, CUtensorMapDataType, cuuint32_t, void*,
    const cuuint64_t*, const cuuint64_t*, const cuuint32_t*, const cuuint32_t*,
    CUtensorMapInterleave, CUtensorMapSwizzle, CUtensorMapL2promotion,
    CUtensorMapFloatOOBfill);

extern "C" void kernel_launch(void* const* d_in, const int* in_sizes, int n_in,
                              void* d_out, int out_size) {
    const float* x = (const float*)d_in[0];
    const float* w = (const float*)d_in[1];
    const void* mask = d_in[2];
    float* out = (float*)d_out;

    void* pA = nullptr;
    void* pB = nullptr;
    cudaGetSymbolAddress(&pA, g_A);
    cudaGetSymbolAddress(&pB, g_B);

    void* fn = nullptr;
    cudaDriverEntryPointQueryResult qres;
    cudaGetDriverEntryPoint("cuTensorMapEncodeTiled", &fn,
                            cudaEnableDefault, &qres);
    PFN_tmEncode tmEncode = (PFN_tmEncode)fn;

    CUtensorMap tmA, tmB;
    {
        cuuint64_t dims[2] = {(cuuint64_t)KDIM, (cuuint64_t)MDIM};
        cuuint64_t strides[1] = {(cuuint64_t)KDIM * 2};
        cuuint32_t box[2] = {(cuuint32_t)BK, (cuuint32_t)BM};   // 32 x 256
        cuuint32_t estr[2] = {1, 1};
        tmEncode(&tmA, CU_TENSOR_MAP_DATA_TYPE_FLOAT16, 2, pA,
                 dims, strides, box, estr,
                 CU_TENSOR_MAP_INTERLEAVE_NONE, CU_TENSOR_MAP_SWIZZLE_64B,
                 CU_TENSOR_MAP_L2_PROMOTION_L2_128B,
                 CU_TENSOR_MAP_FLOAT_OOB_FILL_NONE);
    }
    {
        cuuint64_t dims[2] = {(cuuint64_t)KDIM, (cuuint64_t)NDIM};
        cuuint64_t strides[1] = {(cuuint64_t)KDIM * 2};
        cuuint32_t box[2] = {(cuuint32_t)BK, (cuuint32_t)BN};   // 32 x 256
        cuuint32_t estr[2] = {1, 1};
        tmEncode(&tmB, CU_TENSOR_MAP_DATA_TYPE_FLOAT16, 2, pB,
                 dims, strides, box, estr,
                 CU_TENSOR_MAP_INTERLEAVE_NONE, CU_TENSOR_MAP_SWIZZLE_64B,
                 CU_TENSOR_MAP_L2_PROMOTION_L2_128B,
                 CU_TENSOR_MAP_FLOAT_OOB_FILL_NONE);
    }

    cudaFuncSetAttribute(sparse_gemm_kernel,
                         cudaFuncAttributeMaxDynamicSharedMemorySize,
                         SMEM_DYN_BYTES);

    int nsm = 148;
    cudaDeviceGetAttribute(&nsm, cudaDevAttrMultiProcessorCount, 0);
    int grid = nsm < NTILES ? nsm : NTILES;

    detect_mask_kernel<<<1, 256>>>((const uint4*)mask);
    convert_x_kernel<<<4096, 256>>>(x);
    convert_w_kernel<<<2048, 256>>>(w, mask);

    sparse_gemm_kernel<<<grid, THREADS, SMEM_DYN_BYTES>>>(out, tmA, tmB);
}

// round 14
// speedup vs baseline: 1.2972x; 1.0360x over previous
#include <cuda_runtime.h>
#include <cuda.h>
#include <cuda_fp16.h>
#include <cstdint>

// ============================================================================
// SparseLinear: out[8192,4096] = x[8192,4096] @ (weight*mask)[4096,4096]^T
// fp16 staging + tcgen05 kind::f16 GEMM (sm_103a cubin pass), fp32 TMEM acc.
//
// R14: L2-delivery-bound (p~760cyc = 32KB / ~43 B/cyc/SM = LTS cap/SM).
// Cut bytes 2x with TMA multicast over a 4-CTA cluster (2x2 tile quad):
// A halves multicast along rn-pairs, B halves along rm-pairs. Stage-reuse
// gated by tcgen05.commit multicast (mask 0xF, mma mbar count 4).
// grid=128 (32 clusters, all resident), 4 quads/cluster, zero imbalance.
// ============================================================================

#define MDIM 8192
#define NDIM 4096
#define KDIM 4096
#define BM 256
#define BN 256
#define BK 32
#define NKT (KDIM / BK)   // 128
#define NT_TILES (NDIM / BN)              // 16
#define MT_TILES (MDIM / BM)              // 32
#define NTILES (NT_TILES * MT_TILES)      // 512
#define QN (NT_TILES / 2)                 // 8
#define QM (MT_TILES / 2)                 // 16
#define NQUADS (QN * QM)                  // 128
#define THREADS 288
#define STAGES 7

__device__ __align__(1024) __half g_A[(size_t)MDIM * KDIM];  // x as fp16
__device__ __align__(1024) __half g_B[(size_t)NDIM * KDIM];  // (w*mask) as fp16
__device__ int g_mask_mode;  // 0 = uint8, 1 = int32, 2 = float32

// ---------------------------------------------------------------------------
// Helpers
// ---------------------------------------------------------------------------
__device__ __forceinline__ uint32_t smem_u32(const void* p) {
    uint32_t a;
    asm("{ .reg .u64 t; cvta.to.shared.u64 t, %1; cvt.u32.u64 %0, t; }"
        : "=r"(a) : "l"(p));
    return a;
}

// ---------------------------------------------------------------------------
// Mask dtype detection: coalesced uint4 scan of first 64KB.
// ---------------------------------------------------------------------------
__global__ void detect_mask_kernel(const uint4* __restrict__ m) {
    __shared__ int cnt[4];
    if (threadIdx.x < 4) cnt[threadIdx.x] = 0;
    __syncthreads();
    int local[4] = {0, 0, 0, 0};
#pragma unroll
    for (int i = 0; i < 16; i++) {
        uint4 v = m[threadIdx.x + i * 256];
        uint32_t ws[4] = {v.x, v.y, v.z, v.w};
#pragma unroll
        for (int q = 0; q < 4; q++) {
#pragma unroll
            for (int bpos = 0; bpos < 4; bpos++)
                local[bpos] += ((ws[q] >> (8 * bpos)) & 0xFF) ? 1 : 0;
        }
    }
#pragma unroll
    for (int j = 0; j < 4; j++)
        if (local[j]) atomicAdd(&cnt[j], local[j]);
    __syncthreads();
    if (threadIdx.x == 0) {
        int mode;
        if (cnt[1] == 0 && cnt[2] == 0 && cnt[3] == 0) mode = 1;       // int32
        else if (cnt[0] == 0 && cnt[1] == 0)          mode = 2;       // float32
        else                                           mode = 0;       // uint8
        g_mask_mode = mode;
    }
}

// ---------------------------------------------------------------------------
// Prep: f32 -> fp16 conversions
// ---------------------------------------------------------------------------
__global__ void convert_x_kernel(const float* __restrict__ x) {
    const size_t n4 = (size_t)MDIM * KDIM / 4;
    const float4* x4 = (const float4*)x;
    __half2* o = (__half2*)g_A;
    size_t stride = (size_t)gridDim.x * blockDim.x;
    for (size_t j = (size_t)blockIdx.x * blockDim.x + threadIdx.x; j < n4; j += stride) {
        float4 v = x4[j];
        o[2 * j + 0] = __floats2half2_rn(v.x, v.y);
        o[2 * j + 1] = __floats2half2_rn(v.z, v.w);
    }
}

__global__ void convert_w_kernel(const float* __restrict__ w,
                                 const void* __restrict__ mask) {
    const size_t n4 = (size_t)NDIM * KDIM / 4;
    const float4* w4 = (const float4*)w;
    __half2* o = (__half2*)g_B;
    const int mode = g_mask_mode;
    size_t stride = (size_t)gridDim.x * blockDim.x;
    for (size_t j = (size_t)blockIdx.x * blockDim.x + threadIdx.x; j < n4; j += stride) {
        float4 v = w4[j];
        bool k0, k1, k2, k3;
        if (mode == 0) {
            uchar4 m = ((const uchar4*)mask)[j];
            k0 = m.x; k1 = m.y; k2 = m.z; k3 = m.w;
        } else if (mode == 1) {
            int4 m = ((const int4*)mask)[j];
            k0 = m.x; k1 = m.y; k2 = m.z; k3 = m.w;
        } else {
            float4 m = ((const float4*)mask)[j];
            k0 = m.x != 0.f; k1 = m.y != 0.f; k2 = m.z != 0.f; k3 = m.w != 0.f;
        }
        float a = k0 ? v.x : 0.0f;
        float b = k1 ? v.y : 0.0f;
        float c = k2 ? v.z : 0.0f;
        float d = k3 ? v.w : 0.0f;
        o[2 * j + 0] = __floats2half2_rn(a, b);
        o[2 * j + 1] = __floats2half2_rn(c, d);
    }
}

// ---------------------------------------------------------------------------
// tcgen05-only helpers (compiled on the sm_103a cubin pass)
// ---------------------------------------------------------------------------
#if defined(__CUDA_ARCH_FEAT_SM103_ALL)
__device__ __forceinline__ bool elect_one() {
    uint32_t p;
    asm volatile(
        "{\n\t.reg .pred p;\n\t"
        "elect.sync _|p, 0xFFFFFFFF;\n\t"
        "selp.b32 %0, 1, 0, p;\n\t}"
        : "=r"(p));
    return p != 0;
}
__device__ __forceinline__ uint32_t ctarank() {
    uint32_t r;
    asm("mov.u32 %0, %%cluster_ctarank;" : "=r"(r));
    return r;
}
__device__ __forceinline__ void mbar_init(uint32_t mbar, uint32_t cnt) {
    asm volatile("mbarrier.init.shared.b64 [%0], %1;" :: "r"(mbar), "r"(cnt) : "memory");
}
__device__ __forceinline__ void mbar_wait(uint32_t mbar, uint32_t parity) {
    asm volatile(
        "{\n\t.reg .pred P1;\n\t"
        "WAIT_%=:\n\t"
        "mbarrier.try_wait.parity.acquire.cta.shared::cta.b64 P1, [%0], %1, 0x989680;\n\t"
        "@P1 bra.uni DONE_%=;\n\t"
        "bra.uni WAIT_%=;\n\t"
        "DONE_%=:\n\t}"
        :: "r"(mbar), "r"(parity) : "memory");
}
__device__ __forceinline__ void mbar_expect_tx(uint32_t mbar, uint32_t bytes) {
    asm volatile("mbarrier.arrive.expect_tx.shared.b64 _, [%0], %1;"
                 :: "r"(mbar), "r"(bytes) : "memory");
}
__device__ __forceinline__ void tma_load_2d_mc(uint32_t smem, const void* tm,
                                               int32_t x, int32_t y,
                                               uint32_t mbar, uint16_t mask) {
    asm volatile(
        "cp.async.bulk.tensor.2d.shared::cluster.global.tile."
        "mbarrier::complete_tx::bytes.multicast::cluster "
        "[%0], [%1, {%2, %3}], [%4], %5;"
        :: "r"(smem), "l"(tm), "r"(x), "r"(y), "r"(mbar), "h"(mask) : "memory");
}
// SW64 K-major descriptor: layout=4, version=1, SBO=32, LBO=1.
__device__ __forceinline__ uint64_t make_desc_sw64(uint32_t addr) {
    uint64_t d = (uint64_t(4) << 61) | (uint64_t(1) << 46) |
                 (uint64_t(32) << 32) | (uint64_t(1) << 16);
    return d | ((uint64_t)(addr >> 4) & 0x3FFF);
}
// idesc: dtype=F32, f16 inputs, N=256, M=128 per dispatch
#define MMA_IDESC ((1u << 4) | ((BN / 8) << 17) | ((128 / 16) << 24))
#endif

// ---------------------------------------------------------------------------
// GEMM kernel — persistent, warp-specialized, 4-CTA cluster multicast
// ---------------------------------------------------------------------------
#define A_STAGE_BYTES (BM * 64)                        // 16KB (rows of 64B)
#define B_STAGE_BYTES (BN * 64)                        // 16KB
#define A_HALF (A_STAGE_BYTES / 2)                     // 8KB
#define B_HALF (B_STAGE_BYTES / 2)                     // 8KB
#define STAGE_BYTES (A_STAGE_BYTES + B_STAGE_BYTES)    // 32KB
#define SMEM_DYN_BYTES (STAGES * STAGE_BYTES + 1024)   // ~225KB

__global__ void __launch_bounds__(THREADS)
sparse_gemm_kernel(float* __restrict__ out,
                   const __grid_constant__ CUtensorMap tmA,
                   const __grid_constant__ CUtensorMap tmB) {
    extern __shared__ char dsmem[];
    const int tid = threadIdx.x;
    const int wid = tid >> 5;
    const int lid = tid & 31;

    const uint32_t tiles = (smem_u32(dsmem) + 1023u) & ~1023u;

#if defined(__CUDA_ARCH_FEAT_SM103_ALL)
    // ======================= tcgen05 + TMA-MC path =========================
    __shared__ uint64_t s_full[STAGES];   // TMA completion (expect_tx, cnt 1)
    __shared__ uint64_t s_mma[STAGES];    // MMA completion (4 mc commits)
    __shared__ uint32_t s_tmem_ptr;

    const uint32_t rank = ctarank();      // 0..3
    const int rm = (int)(rank >> 1);      // M offset within quad
    const int rn = (int)(rank & 1);       // N offset within quad
    const uint16_t maskA = (uint16_t)(0x3u << (2 * rm));   // A-sharing pair
    const uint16_t maskB = (uint16_t)(0x5u << rn);         // B-sharing pair
    const int NC = gridDim.x >> 2;        // clusters
    const int cc = blockIdx.x >> 2;       // cluster id

    if (wid == 0) {
        asm volatile("tcgen05.alloc.cta_group::1.sync.aligned.shared::cta.b32 [%0], %1;"
                     :: "r"(smem_u32(&s_tmem_ptr)), "r"(512) : "memory");
        asm volatile("tcgen05.relinquish_alloc_permit.cta_group::1.sync.aligned;");
    }
    if (tid == 0) {
#pragma unroll
        for (int s = 0; s < STAGES; s++) {
            mbar_init(smem_u32(&s_full[s]), 1);
            mbar_init(smem_u32(&s_mma[s]), 4);    // 4 multicast commits/slot
        }
        asm volatile("fence.proxy.async.shared::cta;" ::: "memory");
    }
    __syncthreads();
    // All cluster CTAs' barriers must be live before any multicast targets them.
    asm volatile("barrier.cluster.arrive.aligned;" ::: "memory");
    asm volatile("barrier.cluster.wait.aligned;" ::: "memory");

    uint32_t tmem;
    asm volatile("ld.shared.b32 %0, [%1];" : "=r"(tmem) : "r"(smem_u32(&s_tmem_ptr)));
    const uint32_t d0 = tmem;            // D rows [0,128)   TMEM cols [0,256)
    const uint32_t d1 = tmem + 256;      // D rows [128,256) TMEM cols [256,512)

    if (wid == 8) {
        // =================== PRODUCER warp (never joins bar 1) =============
        if (elect_one()) {
            int g = 0;
            for (int q = cc; q < NQUADS; q += NC) {
                const int mt = 2 * (q / QN) + rm;
                const int nt = 2 * (q % QN) + rn;
                for (int kt = 0; kt < NKT; kt++, g++) {
                    const int s = g % STAGES;
                    // Stage s last consumed by slot g-STAGES in ALL 4 CTAs
                    // (commit-multicast gives 4 arrivals on local s_mma[s]).
                    if (g >= STAGES)
                        mbar_wait(smem_u32(&s_mma[s]),
                                  (uint32_t)((g - STAGES) / STAGES) & 1u);
                    const uint32_t sb = tiles + s * STAGE_BYTES;
                    mbar_expect_tx(smem_u32(&s_full[s]), STAGE_BYTES);
                    // My A half (rows rn*128..) -> A-sharing pair (incl. me).
                    tma_load_2d_mc(sb + rn * A_HALF, &tmA,
                                   kt * BK, mt * BM + rn * 128,
                                   smem_u32(&s_full[s]), maskA);
                    // My B half (rows rm*128..) -> B-sharing pair (incl. me).
                    tma_load_2d_mc(sb + A_STAGE_BYTES + rm * B_HALF, &tmB,
                                   kt * BK, nt * BN + rm * 128,
                                   smem_u32(&s_full[s]), maskB);
                }
            }
        }
    } else {
        // ============== MMA issuer (warp 0) + epilogue (warps 0-7) ========
        int it = 0;
        for (int q = cc; q < NQUADS; q += NC, it++) {
            const int mt = 2 * (q / QN) + rm;
            const int nt = 2 * (q % QN) + rn;

            if (wid == 0 && elect_one()) {
                asm volatile("tcgen05.fence::after_thread_sync;" ::: "memory");
                for (int kt = 0; kt < NKT; kt++) {
                    const int g = it * NKT + kt;
                    const int s = g % STAGES;
                    mbar_wait(smem_u32(&s_full[s]), (uint32_t)(g / STAGES) & 1u);

                    const uint32_t stage_base = tiles + s * STAGE_BYTES;
                    uint64_t ad = make_desc_sw64(stage_base);
                    uint64_t ad2 = make_desc_sw64(stage_base + A_HALF);
                    uint64_t bd = make_desc_sw64(stage_base + A_STAGE_BYTES);
#pragma unroll
                    for (int s4 = 0; s4 < 2; s4++) {
                        uint32_t en = !(kt == 0 && s4 == 0);
                        asm volatile(
                            "{\n\t.reg .pred p;\n\t"
                            "setp.ne.u32 p, %4, 0;\n\t"
                            "tcgen05.mma.cta_group::1.kind::f16 [%0], %1, %2, %3, {%5,%5,%5,%5}, p;\n\t}"
                            :: "r"(d0), "l"(ad + 2 * s4), "l"(bd + 2 * s4),
                               "r"(MMA_IDESC), "r"(en), "r"(0u) : "memory");
                        asm volatile(
                            "{\n\t.reg .pred p;\n\t"
                            "setp.ne.u32 p, %4, 0;\n\t"
                            "tcgen05.mma.cta_group::1.kind::f16 [%0], %1, %2, %3, {%5,%5,%5,%5}, p;\n\t}"
                            :: "r"(d1), "l"(ad2 + 2 * s4), "l"(bd + 2 * s4),
                               "r"(MMA_IDESC), "r"(en), "r"(0u) : "memory");
                    }
                    // Commit to s_mma[s] in ALL 4 cluster CTAs.
                    asm volatile(
                        "tcgen05.commit.cta_group::1.mbarrier::arrive::one."
                        "shared::cluster.multicast::cluster.b64 [%0], %1;"
                        :: "r"(smem_u32(&s_mma[s])), "h"((uint16_t)0xF) : "memory");
                }
                // All 4 CTAs' MMAs for this tile's last slot drained.
                const int gl = it * NKT + NKT - 1;
                mbar_wait(smem_u32(&s_mma[gl % STAGES]),
                          (uint32_t)(gl / STAGES) & 1u);
            }

            // Epilogue barrier: warps 0-7 only (producer keeps streaming).
            asm volatile("bar.sync 1, 256;" ::: "memory");
            asm volatile("tcgen05.fence::after_thread_sync;" ::: "memory");

            {
                const int h = wid >> 2;
                const int sw = wid & 3;
                const uint32_t dbase = tmem + h * 256;
                const int m = mt * BM + h * 128 + sw * 32 + lid;
                float* orow = out + (size_t)m * NDIM + nt * BN;
                uint32_t r[32];
#pragma unroll
                for (int c4 = 0; c4 < 8; c4++) {
                    asm volatile(
                        "tcgen05.ld.sync.aligned.32x32b.x32.b32 "
                        "{%0,%1,%2,%3,%4,%5,%6,%7,%8,%9,%10,%11,%12,%13,%14,%15,"
                        "%16,%17,%18,%19,%20,%21,%22,%23,%24,%25,%26,%27,%28,%29,%30,%31}, [%32];"
                        : "=r"(r[0]), "=r"(r[1]), "=r"(r[2]), "=r"(r[3]),
                          "=r"(r[4]), "=r"(r[5]), "=r"(r[6]), "=r"(r[7]),
                          "=r"(r[8]), "=r"(r[9]), "=r"(r[10]), "=r"(r[11]),
                          "=r"(r[12]), "=r"(r[13]), "=r"(r[14]), "=r"(r[15]),
                          "=r"(r[16]), "=r"(r[17]), "=r"(r[18]), "=r"(r[19]),
                          "=r"(r[20]), "=r"(r[21]), "=r"(r[22]), "=r"(r[23]),
                          "=r"(r[24]), "=r"(r[25]), "=r"(r[26]), "=r"(r[27]),
                          "=r"(r[28]), "=r"(r[29]), "=r"(r[30]), "=r"(r[31])
                        : "r"(dbase + c4 * 32));
                    asm volatile("tcgen05.wait::ld.sync.aligned;" ::: "memory");
                    float4* p = (float4*)(orow + c4 * 32);
#pragma unroll
                    for (int qq = 0; qq < 8; qq++)
                        p[qq] = make_float4(__uint_as_float(r[4 * qq + 0]),
                                            __uint_as_float(r[4 * qq + 1]),
                                            __uint_as_float(r[4 * qq + 2]),
                                            __uint_as_float(r[4 * qq + 3]));
                }
                asm volatile("tcgen05.fence::before_thread_sync;" ::: "memory");
            }
            // TMEM free for next tile's MMAs.
            asm volatile("bar.sync 1, 256;" ::: "memory");
        }
    }

    __syncthreads();   // all 9 warps
    // No CTA exits while cluster peers may still multicast into it.
    asm volatile("barrier.cluster.arrive.aligned;" ::: "memory");
    asm volatile("barrier.cluster.wait.aligned;" ::: "memory");
    if (wid == 0)
        asm volatile("tcgen05.dealloc.cta_group::1.sync.aligned.b32 %0, %1;"
                     :: "r"(tmem), "r"(512));

#else
    // ===== fallback (compute_103 PTX pass only; cubin path always used) ====
    (void)tiles;
    for (int t = blockIdx.x; t < NTILES; t += gridDim.x) {
        const int mt = t / NT_TILES;
        const int nt = t % NT_TILES;
        for (int idx = tid; idx < BM * BN; idx += THREADS) {
            int r = idx / BN, c = idx % BN;
            const __half* a = g_A + (size_t)(mt * BM + r) * KDIM;
            const __half* b = g_B + (size_t)(nt * BN + c) * KDIM;
            float s = 0.0f;
            for (int k = 0; k < KDIM; k++)
                s += __half2float(a[k]) * __half2float(b[k]);
            out[(size_t)(mt * BM + r) * NDIM + nt * BN + c] = s;
        }
    }
#endif
}

// ---------------------------------------------------------------------------
// Launch
// ---------------------------------------------------------------------------
typedef CUresult (*PFN_tmEncode)(
    CUtensorMap*, CUtensorMapDataType, cuuint32_t, void*,
    const cuuint64_t*, const cuuint64_t*, const cuuint32_t*, const cuuint32_t*,
    CUtensorMapInterleave, CUtensorMapSwizzle, CUtensorMapL2promotion,
    CUtensorMapFloatOOBfill);

extern "C" void kernel_launch(void* const* d_in, const int* in_sizes, int n_in,
                              void* d_out, int out_size) {
    const float* x = (const float*)d_in[0];
    const float* w = (const float*)d_in[1];
    const void* mask = d_in[2];
    float* out = (float*)d_out;

    void* pA = nullptr;
    void* pB = nullptr;
    cudaGetSymbolAddress(&pA, g_A);
    cudaGetSymbolAddress(&pB, g_B);

    void* fn = nullptr;
    cudaDriverEntryPointQueryResult qres;
    cudaGetDriverEntryPoint("cuTensorMapEncodeTiled", &fn,
                            cudaEnableDefault, &qres);
    PFN_tmEncode tmEncode = (PFN_tmEncode)fn;

    CUtensorMap tmA, tmB;
    {
        cuuint64_t dims[2] = {(cuuint64_t)KDIM, (cuuint64_t)MDIM};
        cuuint64_t strides[1] = {(cuuint64_t)KDIM * 2};
        cuuint32_t box[2] = {(cuuint32_t)BK, 128};   // 32 x 128 half-tile
        cuuint32_t estr[2] = {1, 1};
        tmEncode(&tmA, CU_TENSOR_MAP_DATA_TYPE_FLOAT16, 2, pA,
                 dims, strides, box, estr,
                 CU_TENSOR_MAP_INTERLEAVE_NONE, CU_TENSOR_MAP_SWIZZLE_64B,
                 CU_TENSOR_MAP_L2_PROMOTION_L2_128B,
                 CU_TENSOR_MAP_FLOAT_OOB_FILL_NONE);
    }
    {
        cuuint64_t dims[2] = {(cuuint64_t)KDIM, (cuuint64_t)NDIM};
        cuuint64_t strides[1] = {(cuuint64_t)KDIM * 2};
        cuuint32_t box[2] = {(cuuint32_t)BK, 128};   // 32 x 128 half-tile
        cuuint32_t estr[2] = {1, 1};
        tmEncode(&tmB, CU_TENSOR_MAP_DATA_TYPE_FLOAT16, 2, pB,
                 dims, strides, box, estr,
                 CU_TENSOR_MAP_INTERLEAVE_NONE, CU_TENSOR_MAP_SWIZZLE_64B,
                 CU_TENSOR_MAP_L2_PROMOTION_L2_128B,
                 CU_TENSOR_MAP_FLOAT_OOB_FILL_NONE);
    }

    cudaFuncSetAttribute(sparse_gemm_kernel,
                         cudaFuncAttributeMaxDynamicSharedMemorySize,
                         SMEM_DYN_BYTES);

    detect_mask_kernel<<<1, 256>>>((const uint4*)mask);
    convert_x_kernel<<<4096, 256>>>(x);
    convert_w_kernel<<<2048, 256>>>(w, mask);

    // 128 CTAs = 32 clusters of 4 (all resident; csz-4 active limit is 132).
    cudaLaunchConfig_t config = {};
    config.gridDim = dim3(128, 1, 1);
    config.blockDim = dim3(THREADS, 1, 1);
    config.dynamicSmemBytes = SMEM_DYN_BYTES;
    cudaLaunchAttribute attrs[1];
    attrs[0].id = cudaLaunchAttributeClusterDimension;
    attrs[0].val.clusterDim.x = 4;
    attrs[0].val.clusterDim.y = 1;
    attrs[0].val.clusterDim.z = 1;
    config.attrs = attrs;
    config.numAttrs = 1;
    cudaLaunchKernelEx(&config, sparse_gemm_kernel, out, tmA, tmB);
}